// round 1
// baseline (speedup 1.0000x reference)
#include <cuda_runtime.h>
#include <math.h>

#define Bb   2
#define Ss   2048
#define Hh   4096
#define NHh  32
#define HDd  128
#define KVHh 8

// Scratch (allocation-free: __device__ globals)
__device__ float g_q[Bb*Ss*NHh*HDd];        // (B*S, 32, 128)
__device__ float g_kv[Bb*Ss*KVHh*2*HDd];    // (B*S, 8, 256)  k|v interleaved per kv-head
__device__ float g_ctx[Bb*Ss*Hh];           // (B*S, 4096)
__device__ float g_cos[Ss*64];
__device__ float g_sin[Ss*64];

// ---------------------------------------------------------------------------
// RoPE tables. S=2048 < TRAINING_SEQLEN=8192 -> ntk_alpha=1, mscale=1, base=1e4
// Match numpy: angle computed/rounded in fp32, cos/sin evaluated accurately.
// ---------------------------------------------------------------------------
__global__ void rope_table_kernel() {
    int idx = blockIdx.x * blockDim.x + threadIdx.x;
    if (idx >= Ss * 64) return;
    int s = idx >> 6, j = idx & 63;
    double invf = exp(-(double)j * (log(10000.0) / 64.0));
    float th = (float)s * (float)invf;           // fp32 rounding like np.outer
    g_cos[idx] = (float)cos((double)th);
    g_sin[idx] = (float)sin((double)th);
}

// In-place RoPE on q and k (k lives in first 128 cols of each 256-wide kv row)
__global__ void rope_apply_kernel() {
    int idx = blockIdx.x * blockDim.x + threadIdx.x;
    if (idx >= Bb * Ss * (NHh + KVHh) * 64) return;
    int j    = idx & 63;
    int t    = idx >> 6;
    int head = t % (NHh + KVHh);
    int row  = t / (NHh + KVHh);
    int s    = row & (Ss - 1);
    float c  = g_cos[(s << 6) + j];
    float sn = g_sin[(s << 6) + j];
    float* base;
    if (head < NHh) base = g_q  + ((size_t)row * NHh + head) * HDd;
    else            base = g_kv + ((size_t)row * KVHh + (head - NHh)) * (2 * HDd);
    float x1 = base[j], x2 = base[j + 64];
    base[j]      = x1 * c - x2 * sn;
    base[j + 64] = x2 * c + x1 * sn;
}

// ---------------------------------------------------------------------------
// Packed fp32x2 helpers (Blackwell FFMA2 — PTX-only, ptxas never auto-fuses)
// ---------------------------------------------------------------------------
__device__ __forceinline__ unsigned long long pk2(float lo, float hi) {
    unsigned long long r;
    asm("mov.b64 %0, {%1, %2};" : "=l"(r)
        : "r"(__float_as_uint(lo)), "r"(__float_as_uint(hi)));
    return r;
}
__device__ __forceinline__ void ffma2(unsigned long long& d,
                                      unsigned long long a, unsigned long long b) {
    asm("fma.rn.f32x2 %0, %1, %2, %0;" : "+l"(d) : "l"(a), "l"(b));
}

// ---------------------------------------------------------------------------
// Tiled fp32 GEMM:  C[M,N] = A[M,K] @ W[K,N]  (+ bias + residual)
// 128x128 block tile, k-step 8, double-buffered smem, 8x8 per-thread tile
// computed as 4 row-pairs x 8 cols of packed f32x2 FMAs.
// M,N multiples of 128; K multiple of 8.
// ---------------------------------------------------------------------------
__global__ void __launch_bounds__(256) gemm128_kernel(
    const float* __restrict__ A, const float* __restrict__ W,
    float* __restrict__ C, int N, int K,
    const float* __restrict__ bias, const float* __restrict__ resid)
{
    __shared__ float As[2][8][128];   // [buf][k][m]  (A stored transposed)
    __shared__ float Bs[2][8][128];   // [buf][k][n]
    const int tid = threadIdx.x;
    const int bm = blockIdx.y * 128, bn = blockIdx.x * 128;
    const int tx = tid & 15, ty = tid >> 4;

    const int arow = tid >> 1, acol = (tid & 1) * 4;   // A: 128 rows x 8 k
    const int brow = tid >> 5, bcol = (tid & 31) * 4;  // B: 8 k x 128 n
    const float* Ag = A + (size_t)(bm + arow) * K + acol;
    const float* Bg = W + (size_t)brow * N + bn + bcol;

    float4 aR = *(const float4*)Ag;
    float4 bR = *(const float4*)Bg;
    As[0][acol + 0][arow] = aR.x; As[0][acol + 1][arow] = aR.y;
    As[0][acol + 2][arow] = aR.z; As[0][acol + 3][arow] = aR.w;
    *(float4*)&Bs[0][brow][bcol] = bR;
    __syncthreads();

    unsigned long long acc2[4][8];
    #pragma unroll
    for (int i = 0; i < 4; ++i)
        #pragma unroll
        for (int j = 0; j < 8; ++j) acc2[i][j] = 0ull;

    const int T = K >> 3;
    int cur = 0;
    for (int t = 0; t < T; ++t) {
        if (t + 1 < T) {
            aR = *(const float4*)(Ag + (size_t)(t + 1) * 8);
            bR = *(const float4*)(Bg + (size_t)(t + 1) * 8 * N);
        }
        #pragma unroll
        for (int kk = 0; kk < 8; ++kk) {
            float4 a0 = *(const float4*)&As[cur][kk][ty * 8];
            float4 a1 = *(const float4*)&As[cur][kk][ty * 8 + 4];
            float4 b0 = *(const float4*)&Bs[cur][kk][tx * 8];
            float4 b1 = *(const float4*)&Bs[cur][kk][tx * 8 + 4];
            unsigned long long ap[4] = { pk2(a0.x, a0.y), pk2(a0.z, a0.w),
                                         pk2(a1.x, a1.y), pk2(a1.z, a1.w) };
            float bs8[8] = { b0.x, b0.y, b0.z, b0.w, b1.x, b1.y, b1.z, b1.w };
            #pragma unroll
            for (int j = 0; j < 8; ++j) {
                unsigned long long bd = pk2(bs8[j], bs8[j]);
                #pragma unroll
                for (int i = 0; i < 4; ++i) ffma2(acc2[i][j], ap[i], bd);
            }
        }
        if (t + 1 < T) {
            int nxt = cur ^ 1;
            As[nxt][acol + 0][arow] = aR.x; As[nxt][acol + 1][arow] = aR.y;
            As[nxt][acol + 2][arow] = aR.z; As[nxt][acol + 3][arow] = aR.w;
            *(float4*)&Bs[nxt][brow][bcol] = bR;
        }
        __syncthreads();
        cur ^= 1;
    }

    const int cn0 = bn + tx * 8;
    #pragma unroll
    for (int i2 = 0; i2 < 4; ++i2) {
        float rv0[8], rv1[8];
        #pragma unroll
        for (int j = 0; j < 8; ++j) {
            union { unsigned long long u; float2 f; } cv;
            cv.u = acc2[i2][j];
            rv0[j] = cv.f.x; rv1[j] = cv.f.y;
        }
        #pragma unroll
        for (int half = 0; half < 2; ++half) {
            int r = bm + ty * 8 + i2 * 2 + half;
            float vv[8];
            #pragma unroll
            for (int j = 0; j < 8; ++j) {
                float v = half ? rv1[j] : rv0[j];
                if (bias)  v += bias[cn0 + j];
                if (resid) v += resid[(size_t)r * N + cn0 + j];
                vv[j] = v;
            }
            *(float4*)&C[(size_t)r * N + cn0]     = make_float4(vv[0], vv[1], vv[2], vv[3]);
            *(float4*)&C[(size_t)r * N + cn0 + 4] = make_float4(vv[4], vv[5], vv[6], vv[7]);
        }
    }
}

// ---------------------------------------------------------------------------
// Flash attention (fp32): per block one (b, head, 64-row Q tile).
// Streams 64-row K/V tiles (causal: kt <= qt). 256 threads (16x16),
// scores 4x4/thread, output 4 rows x 8 cols/thread.
// ---------------------------------------------------------------------------
#define ATTN_SMEM_FLOATS (8192 + 8192 + 8192 + 64*68)
#define ATTN_SMEM_BYTES  (ATTN_SMEM_FLOATS * 4)

__global__ void __launch_bounds__(256) attn_kernel() {
    extern __shared__ float sm[];
    float* Qs = sm;                 // [128][64] transposed
    float* Ks = sm + 8192;          // [128][64] transposed
    float* Vs = sm + 16384;         // [64][128]
    float* Ps = sm + 24576;         // [64][68]  (padded)

    const int tid = threadIdx.x;
    const int tx = tid & 15, ty = tid >> 4;
    const int qt = blockIdx.x, h = blockIdx.y, b = blockIdx.z;
    const int kvh = h >> 2;  // GROUPS = 4
    const float scale = 0.08838834764831845f;  // 1/sqrt(128)

    // Load + scale Q tile, transposed
    {
        const float* qbase = g_q + ((size_t)(b * Ss + qt * 64) * NHh + h) * HDd;
        #pragma unroll
        for (int it = 0; it < 8; ++it) {
            int lin = tid + it * 256;
            int r = lin >> 5, d4 = (lin & 31) << 2;
            float4 v = *(const float4*)(qbase + (size_t)r * NHh * HDd + d4);
            Qs[(d4 + 0) * 64 + r] = v.x * scale;
            Qs[(d4 + 1) * 64 + r] = v.y * scale;
            Qs[(d4 + 2) * 64 + r] = v.z * scale;
            Qs[(d4 + 3) * 64 + r] = v.w * scale;
        }
    }

    float m_i[4], l_i[4], o[4][8];
    #pragma unroll
    for (int i = 0; i < 4; ++i) {
        m_i[i] = -INFINITY; l_i[i] = 0.f;
        #pragma unroll
        for (int j = 0; j < 8; ++j) o[i][j] = 0.f;
    }

    for (int kt = 0; kt <= qt; ++kt) {
        __syncthreads();   // protects Qs (first iter) and Ks/Vs/Ps reuse
        // Load K tile (transposed) and V tile
        const float* kbase = g_kv + ((size_t)(b * Ss + kt * 64) * KVHh + kvh) * 256;
        #pragma unroll
        for (int it = 0; it < 8; ++it) {
            int lin = tid + it * 256;
            int r = lin >> 5, d4 = (lin & 31) << 2;
            const float* rp = kbase + (size_t)r * KVHh * 256;
            float4 kv4 = *(const float4*)(rp + d4);
            Ks[(d4 + 0) * 64 + r] = kv4.x; Ks[(d4 + 1) * 64 + r] = kv4.y;
            Ks[(d4 + 2) * 64 + r] = kv4.z; Ks[(d4 + 3) * 64 + r] = kv4.w;
            float4 vv = *(const float4*)(rp + 128 + d4);
            *(float4*)&Vs[r * 128 + d4] = vv;
        }
        __syncthreads();

        // S = (Q*scale) K^T  -> 4x4 per thread
        float acc[4][4];
        #pragma unroll
        for (int i = 0; i < 4; ++i)
            #pragma unroll
            for (int j = 0; j < 4; ++j) acc[i][j] = 0.f;

        #pragma unroll 8
        for (int d = 0; d < 128; ++d) {
            float4 q4 = *(const float4*)&Qs[d * 64 + ty * 4];
            float4 k4 = *(const float4*)&Ks[d * 64 + tx * 4];
            float qa[4] = { q4.x, q4.y, q4.z, q4.w };
            float ka[4] = { k4.x, k4.y, k4.z, k4.w };
            #pragma unroll
            for (int i = 0; i < 4; ++i)
                #pragma unroll
                for (int j = 0; j < 4; ++j) acc[i][j] += qa[i] * ka[j];
        }

        if (kt == qt) {  // causal mask on diagonal tile
            #pragma unroll
            for (int i = 0; i < 4; ++i)
                #pragma unroll
                for (int j = 0; j < 4; ++j)
                    if (tx * 4 + j > ty * 4 + i) acc[i][j] = -INFINITY;
        }

        // Online softmax per row (16 lanes per row)
        #pragma unroll
        for (int i = 0; i < 4; ++i) {
            float mt = fmaxf(fmaxf(acc[i][0], acc[i][1]), fmaxf(acc[i][2], acc[i][3]));
            #pragma unroll
            for (int off = 8; off >= 1; off >>= 1)
                mt = fmaxf(mt, __shfl_xor_sync(0xffffffffu, mt, off));
            float mn = fmaxf(m_i[i], mt);
            float corr = __expf(m_i[i] - mn);
            float rs = 0.f;
            #pragma unroll
            for (int j = 0; j < 4; ++j) {
                float p = __expf(acc[i][j] - mn);
                acc[i][j] = p; rs += p;
            }
            #pragma unroll
            for (int off = 8; off >= 1; off >>= 1)
                rs += __shfl_xor_sync(0xffffffffu, rs, off);
            l_i[i] = l_i[i] * corr + rs;
            m_i[i] = mn;
            #pragma unroll
            for (int j = 0; j < 8; ++j) o[i][j] *= corr;
            *(float4*)&Ps[(ty * 4 + i) * 68 + tx * 4] =
                make_float4(acc[i][0], acc[i][1], acc[i][2], acc[i][3]);
        }
        __syncthreads();

        // O += P V   (4 rows x 8 cols per thread)
        #pragma unroll 4
        for (int c = 0; c < 64; ++c) {
            float4 v0 = *(const float4*)&Vs[c * 128 + tx * 8];
            float4 v1 = *(const float4*)&Vs[c * 128 + tx * 8 + 4];
            #pragma unroll
            for (int i = 0; i < 4; ++i) {
                float p = Ps[(ty * 4 + i) * 68 + c];
                o[i][0] += p * v0.x; o[i][1] += p * v0.y;
                o[i][2] += p * v0.z; o[i][3] += p * v0.w;
                o[i][4] += p * v1.x; o[i][5] += p * v1.y;
                o[i][6] += p * v1.z; o[i][7] += p * v1.w;
            }
        }
    }

    // Normalize and write ctx
    #pragma unroll
    for (int i = 0; i < 4; ++i) {
        float inv = 1.f / l_i[i];
        int r = qt * 64 + ty * 4 + i;
        float* obase = g_ctx + (size_t)(b * Ss + r) * Hh + h * HDd + tx * 8;
        *(float4*)obase = make_float4(o[i][0] * inv, o[i][1] * inv,
                                      o[i][2] * inv, o[i][3] * inv);
        *(float4*)(obase + 4) = make_float4(o[i][4] * inv, o[i][5] * inv,
                                            o[i][6] * inv, o[i][7] * inv);
    }
}

// ---------------------------------------------------------------------------
extern "C" void kernel_launch(void* const* d_in, const int* in_sizes, int n_in,
                              void* d_out, int out_size) {
    const float* hs  = (const float*)d_in[0];  // hidden_states (B,S,H)
    const float* res = (const float*)d_in[1];  // residual      (B,S,H)
    // d_in[2] = attention_mask (causal; recomputed analytically, ignored)
    const float* Wq  = (const float*)d_in[3];  // (H, H)
    const float* Wkv = (const float*)d_in[4];  // (H, 2*KVH*HD)
    const float* Wd  = (const float*)d_in[5];  // (H, H)
    const float* bd  = (const float*)d_in[6];  // (H,)
    float* out = (float*)d_out;

    float *qp, *kvp, *ctxp;
    cudaGetSymbolAddress((void**)&qp,   g_q);
    cudaGetSymbolAddress((void**)&kvp,  g_kv);
    cudaGetSymbolAddress((void**)&ctxp, g_ctx);
    cudaFuncSetAttribute(attn_kernel,
                         cudaFuncAttributeMaxDynamicSharedMemorySize,
                         ATTN_SMEM_BYTES);

    const int M = Bb * Ss;          // 4096
    const int NKV = 2 * KVHh * HDd; // 2048

    rope_table_kernel<<<(Ss * 64 + 255) / 256, 256>>>();
    gemm128_kernel<<<dim3(Hh / 128, M / 128), 256>>>(hs, Wq, qp, Hh, Hh, nullptr, nullptr);
    gemm128_kernel<<<dim3(NKV / 128, M / 128), 256>>>(hs, Wkv, kvp, NKV, Hh, nullptr, nullptr);
    rope_apply_kernel<<<(Bb * Ss * (NHh + KVHh) * 64 + 255) / 256, 256>>>();
    attn_kernel<<<dim3(Ss / 64, NHh, Bb), 256, ATTN_SMEM_BYTES>>>();
    gemm128_kernel<<<dim3(Hh / 128, M / 128), 256>>>(ctxp, Wd, out, Hh, Hh, bd, res);
}

// round 4
// speedup vs baseline: 1.8590x; 1.8590x over previous
#include <cuda_runtime.h>
#include <math.h>
#include <stdint.h>

#define Bb   2
#define Ss   2048
#define Hh   4096
#define NHh  32
#define HDd  128
#define KVHh 8
#define Mtot (Bb*Ss)          // 4096

// ---------------- scratch (allocation-free) ----------------
__device__ float g_q[Bb*Ss*NHh*HDd];        // (4096, 32,128)
__device__ float g_kv[Bb*Ss*KVHh*2*HDd];    // (4096, 8, 256) k|v
__device__ float g_ctx[Bb*Ss*Hh];           // (4096, 4096) tf32-rounded
__device__ float g_hsr[Mtot*Hh];            // hs rounded to tf32
__device__ float g_wqt[Hh*Hh];              // Wq^T  [N=4096][K=4096] tf32
__device__ float g_wkvt[2*KVHh*HDd*Hh];     // Wkv^T [N=2048][K=4096] tf32
__device__ float g_wdt[Hh*Hh];              // Wd^T tf32
__device__ float g_cos[Ss*64];
__device__ float g_sin[Ss*64];

// ---------------- helpers ----------------
__device__ __forceinline__ uint32_t smem_u32(const void* p) {
    uint32_t a;
    asm("{ .reg .u64 t; cvta.to.shared.u64 t, %1; cvt.u32.u64 %0, t; }" : "=r"(a) : "l"(p));
    return a;
}
__device__ __forceinline__ float rnd_tf32(float x) {
    uint32_t u;
    asm("cvt.rna.tf32.f32 %0, %1;" : "=r"(u) : "f"(x));
    return __uint_as_float(u);
}
#define CP_ASYNC16(dst_u32, src_ptr) \
    asm volatile("cp.async.cg.shared.global [%0], [%1], 16;" :: "r"(dst_u32), "l"(src_ptr) : "memory")
#define CP_COMMIT() asm volatile("cp.async.commit_group;" ::: "memory")
#define CP_WAIT(n)  asm volatile("cp.async.wait_group %0;" :: "n"(n) : "memory")

__device__ __forceinline__ void mma_tf32_16n8k8(float* c, const uint32_t* a, const uint32_t* b) {
    asm volatile(
        "mma.sync.aligned.m16n8k8.row.col.f32.tf32.tf32.f32 "
        "{%0,%1,%2,%3}, {%4,%5,%6,%7}, {%8,%9}, {%0,%1,%2,%3};"
        : "+f"(c[0]), "+f"(c[1]), "+f"(c[2]), "+f"(c[3])
        : "r"(a[0]), "r"(a[1]), "r"(a[2]), "r"(a[3]), "r"(b[0]), "r"(b[1]));
}

// ---------------------------------------------------------------------------
// RoPE
// ---------------------------------------------------------------------------
__global__ void rope_table_kernel() {
    int idx = blockIdx.x * blockDim.x + threadIdx.x;
    if (idx >= Ss * 64) return;
    int s = idx >> 6, j = idx & 63;
    double invf = exp(-(double)j * (log(10000.0) / 64.0));
    float th = (float)s * (float)invf;
    g_cos[idx] = (float)cos((double)th);
    g_sin[idx] = (float)sin((double)th);
}

__global__ void rope_apply_kernel() {
    int idx = blockIdx.x * blockDim.x + threadIdx.x;
    if (idx >= Bb * Ss * (NHh + KVHh) * 64) return;
    int j    = idx & 63;
    int t    = idx >> 6;
    int head = t % (NHh + KVHh);
    int row  = t / (NHh + KVHh);
    int s    = row & (Ss - 1);
    float c  = g_cos[(s << 6) + j];
    float sn = g_sin[(s << 6) + j];
    float* base;
    if (head < NHh) base = g_q  + ((size_t)row * NHh + head) * HDd;
    else            base = g_kv + ((size_t)row * KVHh + (head - NHh)) * (2 * HDd);
    float x1 = base[j], x2 = base[j + 64];
    base[j]      = x1 * c - x2 * sn;
    base[j + 64] = x2 * c + x1 * sn;
}

// ---------------------------------------------------------------------------
// tf32 rounding copy + transpose+round
// ---------------------------------------------------------------------------
__global__ void cvt_rn_kernel(const float* __restrict__ src, float* __restrict__ dst, int n4) {
    int i = blockIdx.x * blockDim.x + threadIdx.x;
    if (i >= n4) return;
    float4 v = ((const float4*)src)[i];
    v.x = rnd_tf32(v.x); v.y = rnd_tf32(v.y); v.z = rnd_tf32(v.z); v.w = rnd_tf32(v.w);
    ((float4*)dst)[i] = v;
}

// src[K][N] row-major -> dst[N][K] row-major, tf32-rounded
__global__ void transpose_rn_kernel(const float* __restrict__ src, float* __restrict__ dst,
                                    int K, int N) {
    __shared__ float t[32][33];
    int k0 = blockIdx.y * 32, n0 = blockIdx.x * 32;
    int tx = threadIdx.x, ty = threadIdx.y;   // 32 x 8
    #pragma unroll
    for (int i = 0; i < 32; i += 8)
        t[ty + i][tx] = src[(size_t)(k0 + ty + i) * N + n0 + tx];
    __syncthreads();
    #pragma unroll
    for (int i = 0; i < 32; i += 8)
        dst[(size_t)(n0 + ty + i) * K + k0 + tx] = rnd_tf32(t[tx][ty + i]);
}

// ---------------------------------------------------------------------------
// tf32 mma.sync GEMM:  C[M,N] = A[M,K] @ B^T  (B stored [N][K], K-major)
// CTA 128x128, K-chunk 32, 3-stage cp.async pipeline, 8 warps (2x4),
// warp tile 64x32 = 4x4 m16n8k8 tiles.
// Smem tiles row-major [128][36] (pad 4) -> conflict-free fragment gathers.
// ---------------------------------------------------------------------------
#define BM 128
#define BN 128
#define BK 32
#define STG 3
#define LDT 36
#define TILEF (BM * LDT)                 // floats per tile per stage
#define GSMEM_BYTES (STG * 2 * TILEF * 4)  // 110592

__global__ void __launch_bounds__(256) gemm_mma_kernel(
    const float* __restrict__ A, const float* __restrict__ Bt,
    float* __restrict__ C, int N, int K,
    const float* __restrict__ bias, const float* __restrict__ resid)
{
    extern __shared__ float sm[];
    float* As = sm;                 // [STG][BM][LDT]
    float* Bs = sm + STG * TILEF;   // [STG][BN][LDT]
    const uint32_t as_u = smem_u32(As);
    const uint32_t bs_u = smem_u32(Bs);

    const int tid  = threadIdx.x;
    const int bm   = blockIdx.y * BM, bn = blockIdx.x * BN;
    const int warp = tid >> 5, lane = tid & 31;
    const int g    = lane >> 2, t4 = lane & 3;
    const int wm   = (warp & 1) * 64, wn = (warp >> 1) * 32;

    const int NC = K / BK;   // k-chunks

    auto load_stage = [&](int s, int c) {
        const float* Aptr = A  + (size_t)bm * K + (size_t)c * BK;
        const float* Bptr = Bt + (size_t)bn * K + (size_t)c * BK;
        #pragma unroll
        for (int i = 0; i < 4; ++i) {
            int idx = tid + i * 256;
            int row = idx >> 3, seg = idx & 7;
            uint32_t so = (uint32_t)((s * TILEF + row * LDT + seg * 4) * 4);
            CP_ASYNC16(as_u + so, Aptr + (size_t)row * K + seg * 4);
            CP_ASYNC16(bs_u + so, Bptr + (size_t)row * K + seg * 4);
        }
    };

    float acc[4][4][4];
    #pragma unroll
    for (int mi = 0; mi < 4; ++mi)
        #pragma unroll
        for (int ni = 0; ni < 4; ++ni)
            #pragma unroll
            for (int r = 0; r < 4; ++r) acc[mi][ni][r] = 0.f;

    #pragma unroll
    for (int s = 0; s < STG - 1; ++s) { load_stage(s, s); CP_COMMIT(); }

    for (int c = 0; c < NC; ++c) {
        CP_WAIT(STG - 2);
        __syncthreads();
        if (c + STG - 1 < NC) load_stage((c + STG - 1) % STG, c + STG - 1);
        CP_COMMIT();

        const float* Ap = As + (c % STG) * TILEF + (wm + g) * LDT;
        const float* Bp = Bs + (c % STG) * TILEF + (wn + g) * LDT;
        #pragma unroll
        for (int ks = 0; ks < 4; ++ks) {
            const int k0 = ks * 8 + t4;
            uint32_t af[4][4], bf[4][2];
            #pragma unroll
            for (int mi = 0; mi < 4; ++mi) {
                const float* p = Ap + mi * 16 * LDT;
                af[mi][0] = __float_as_uint(p[k0]);
                af[mi][1] = __float_as_uint(p[8 * LDT + k0]);
                af[mi][2] = __float_as_uint(p[k0 + 4]);
                af[mi][3] = __float_as_uint(p[8 * LDT + k0 + 4]);
            }
            #pragma unroll
            for (int ni = 0; ni < 4; ++ni) {
                const float* p = Bp + ni * 8 * LDT;
                bf[ni][0] = __float_as_uint(p[k0]);
                bf[ni][1] = __float_as_uint(p[k0 + 4]);
            }
            #pragma unroll
            for (int mi = 0; mi < 4; ++mi)
                #pragma unroll
                for (int ni = 0; ni < 4; ++ni)
                    mma_tf32_16n8k8(acc[mi][ni], af[mi], bf[ni]);
        }
    }

    // epilogue
    #pragma unroll
    for (int mi = 0; mi < 4; ++mi) {
        #pragma unroll
        for (int half = 0; half < 2; ++half) {
            int row = bm + wm + mi * 16 + g + half * 8;
            float* crow = C + (size_t)row * N;
            const float* rrow = resid ? resid + (size_t)row * N : nullptr;
            #pragma unroll
            for (int ni = 0; ni < 4; ++ni) {
                int col = bn + wn + ni * 8 + 2 * t4;
                float v0 = acc[mi][ni][half * 2 + 0];
                float v1 = acc[mi][ni][half * 2 + 1];
                if (bias) { v0 += bias[col]; v1 += bias[col + 1]; }
                if (rrow) { v0 += rrow[col]; v1 += rrow[col + 1]; }
                *(float2*)&crow[col] = make_float2(v0, v1);
            }
        }
    }
}

// ---------------------------------------------------------------------------
// Flash attention (fp32 SIMT; ctx store rounded to tf32)
// ---------------------------------------------------------------------------
#define ATTN_SMEM_FLOATS (8192 + 8192 + 8192 + 64*68)
#define ATTN_SMEM_BYTES  (ATTN_SMEM_FLOATS * 4)

__global__ void __launch_bounds__(256) attn_kernel() {
    extern __shared__ float smf[];
    float* Qs = smf;
    float* Ks = smf + 8192;
    float* Vs = smf + 16384;
    float* Ps = smf + 24576;

    const int tid = threadIdx.x;
    const int tx = tid & 15, ty = tid >> 4;
    const int qt = blockIdx.x, h = blockIdx.y, b = blockIdx.z;
    const int kvh = h >> 2;
    const float scale = 0.08838834764831845f;

    {
        const float* qbase = g_q + ((size_t)(b * Ss + qt * 64) * NHh + h) * HDd;
        #pragma unroll
        for (int it = 0; it < 8; ++it) {
            int lin = tid + it * 256;
            int r = lin >> 5, d4 = (lin & 31) << 2;
            float4 v = *(const float4*)(qbase + (size_t)r * NHh * HDd + d4);
            Qs[(d4 + 0) * 64 + r] = v.x * scale;
            Qs[(d4 + 1) * 64 + r] = v.y * scale;
            Qs[(d4 + 2) * 64 + r] = v.z * scale;
            Qs[(d4 + 3) * 64 + r] = v.w * scale;
        }
    }

    float m_i[4], l_i[4], o[4][8];
    #pragma unroll
    for (int i = 0; i < 4; ++i) {
        m_i[i] = -INFINITY; l_i[i] = 0.f;
        #pragma unroll
        for (int j = 0; j < 8; ++j) o[i][j] = 0.f;
    }

    for (int kt = 0; kt <= qt; ++kt) {
        __syncthreads();
        const float* kbase = g_kv + ((size_t)(b * Ss + kt * 64) * KVHh + kvh) * 256;
        #pragma unroll
        for (int it = 0; it < 8; ++it) {
            int lin = tid + it * 256;
            int r = lin >> 5, d4 = (lin & 31) << 2;
            const float* rp = kbase + (size_t)r * KVHh * 256;
            float4 kv4 = *(const float4*)(rp + d4);
            Ks[(d4 + 0) * 64 + r] = kv4.x; Ks[(d4 + 1) * 64 + r] = kv4.y;
            Ks[(d4 + 2) * 64 + r] = kv4.z; Ks[(d4 + 3) * 64 + r] = kv4.w;
            float4 vv = *(const float4*)(rp + 128 + d4);
            *(float4*)&Vs[r * 128 + d4] = vv;
        }
        __syncthreads();

        float acc[4][4];
        #pragma unroll
        for (int i = 0; i < 4; ++i)
            #pragma unroll
            for (int j = 0; j < 4; ++j) acc[i][j] = 0.f;

        #pragma unroll 8
        for (int d = 0; d < 128; ++d) {
            float4 q4 = *(const float4*)&Qs[d * 64 + ty * 4];
            float4 k4 = *(const float4*)&Ks[d * 64 + tx * 4];
            float qa[4] = { q4.x, q4.y, q4.z, q4.w };
            float ka[4] = { k4.x, k4.y, k4.z, k4.w };
            #pragma unroll
            for (int i = 0; i < 4; ++i)
                #pragma unroll
                for (int j = 0; j < 4; ++j) acc[i][j] += qa[i] * ka[j];
        }

        if (kt == qt) {
            #pragma unroll
            for (int i = 0; i < 4; ++i)
                #pragma unroll
                for (int j = 0; j < 4; ++j)
                    if (tx * 4 + j > ty * 4 + i) acc[i][j] = -INFINITY;
        }

        #pragma unroll
        for (int i = 0; i < 4; ++i) {
            float mt = fmaxf(fmaxf(acc[i][0], acc[i][1]), fmaxf(acc[i][2], acc[i][3]));
            #pragma unroll
            for (int off = 8; off >= 1; off >>= 1)
                mt = fmaxf(mt, __shfl_xor_sync(0xffffffffu, mt, off));
            float mn = fmaxf(m_i[i], mt);
            float corr = __expf(m_i[i] - mn);
            float rs = 0.f;
            #pragma unroll
            for (int j = 0; j < 4; ++j) {
                float p = __expf(acc[i][j] - mn);
                acc[i][j] = p; rs += p;
            }
            #pragma unroll
            for (int off = 8; off >= 1; off >>= 1)
                rs += __shfl_xor_sync(0xffffffffu, rs, off);
            l_i[i] = l_i[i] * corr + rs;
            m_i[i] = mn;
            #pragma unroll
            for (int j = 0; j < 8; ++j) o[i][j] *= corr;
            *(float4*)&Ps[(ty * 4 + i) * 68 + tx * 4] =
                make_float4(acc[i][0], acc[i][1], acc[i][2], acc[i][3]);
        }
        __syncthreads();

        #pragma unroll 4
        for (int c = 0; c < 64; ++c) {
            float4 v0 = *(const float4*)&Vs[c * 128 + tx * 8];
            float4 v1 = *(const float4*)&Vs[c * 128 + tx * 8 + 4];
            #pragma unroll
            for (int i = 0; i < 4; ++i) {
                float p = Ps[(ty * 4 + i) * 68 + c];
                o[i][0] += p * v0.x; o[i][1] += p * v0.y;
                o[i][2] += p * v0.z; o[i][3] += p * v0.w;
                o[i][4] += p * v1.x; o[i][5] += p * v1.y;
                o[i][6] += p * v1.z; o[i][7] += p * v1.w;
            }
        }
    }

    #pragma unroll
    for (int i = 0; i < 4; ++i) {
        float inv = 1.f / l_i[i];
        int r = qt * 64 + ty * 4 + i;
        float* obase = g_ctx + (size_t)(b * Ss + r) * Hh + h * HDd + tx * 8;
        *(float4*)obase = make_float4(rnd_tf32(o[i][0] * inv), rnd_tf32(o[i][1] * inv),
                                      rnd_tf32(o[i][2] * inv), rnd_tf32(o[i][3] * inv));
        *(float4*)(obase + 4) = make_float4(rnd_tf32(o[i][4] * inv), rnd_tf32(o[i][5] * inv),
                                            rnd_tf32(o[i][6] * inv), rnd_tf32(o[i][7] * inv));
    }
}

// ---------------------------------------------------------------------------
extern "C" void kernel_launch(void* const* d_in, const int* in_sizes, int n_in,
                              void* d_out, int out_size) {
    const float* hs  = (const float*)d_in[0];
    const float* res = (const float*)d_in[1];
    const float* Wq  = (const float*)d_in[3];
    const float* Wkv = (const float*)d_in[4];
    const float* Wd  = (const float*)d_in[5];
    const float* bd  = (const float*)d_in[6];
    float* out = (float*)d_out;

    float *qp, *kvp, *ctxp, *hsr, *wqt, *wkvt, *wdt;
    cudaGetSymbolAddress((void**)&qp,   g_q);
    cudaGetSymbolAddress((void**)&kvp,  g_kv);
    cudaGetSymbolAddress((void**)&ctxp, g_ctx);
    cudaGetSymbolAddress((void**)&hsr,  g_hsr);
    cudaGetSymbolAddress((void**)&wqt,  g_wqt);
    cudaGetSymbolAddress((void**)&wkvt, g_wkvt);
    cudaGetSymbolAddress((void**)&wdt,  g_wdt);

    cudaFuncSetAttribute(attn_kernel, cudaFuncAttributeMaxDynamicSharedMemorySize, ATTN_SMEM_BYTES);
    cudaFuncSetAttribute(gemm_mma_kernel, cudaFuncAttributeMaxDynamicSharedMemorySize, GSMEM_BYTES);

    const int NKV = 2 * KVHh * HDd;   // 2048

    rope_table_kernel<<<(Ss * 64 + 255) / 256, 256>>>();
    cvt_rn_kernel<<<(Mtot * Hh / 4 + 255) / 256, 256>>>(hs, hsr, Mtot * Hh / 4);
    transpose_rn_kernel<<<dim3(Hh / 32, Hh / 32), dim3(32, 8)>>>(Wq,  wqt,  Hh, Hh);
    transpose_rn_kernel<<<dim3(NKV / 32, Hh / 32), dim3(32, 8)>>>(Wkv, wkvt, Hh, NKV);
    transpose_rn_kernel<<<dim3(Hh / 32, Hh / 32), dim3(32, 8)>>>(Wd,  wdt,  Hh, Hh);

    gemm_mma_kernel<<<dim3(Hh / BN, Mtot / BM), 256, GSMEM_BYTES>>>(hsr, wqt, qp, Hh, Hh, nullptr, nullptr);
    gemm_mma_kernel<<<dim3(NKV / BN, Mtot / BM), 256, GSMEM_BYTES>>>(hsr, wkvt, kvp, NKV, Hh, nullptr, nullptr);

    rope_apply_kernel<<<(Bb * Ss * (NHh + KVHh) * 64 + 255) / 256, 256>>>();
    attn_kernel<<<dim3(Ss / 64, NHh, Bb), 256, ATTN_SMEM_BYTES>>>();

    gemm_mma_kernel<<<dim3(Hh / BN, Mtot / BM), 256, GSMEM_BYTES>>>(ctxp, wdt, out, Hh, Hh, bd, res);
}

// round 5
// speedup vs baseline: 3.3400x; 1.7967x over previous
#include <cuda_runtime.h>
#include <math.h>
#include <stdint.h>

#define Bb   2
#define Ss   2048
#define Hh   4096
#define NHh  32
#define HDd  128
#define KVHh 8
#define Mtot (Bb*Ss)          // 4096

// ---------------- scratch (allocation-free) ----------------
__device__ float g_q[Bb*Ss*NHh*HDd];        // post-RoPE, tf32-rounded
__device__ float g_kv[Bb*Ss*KVHh*2*HDd];    // k|v; k tf32-rounded post-RoPE
__device__ float g_vt[Bb*KVHh*HDd*Ss];      // V transposed [b][kvh][d][s], tf32
__device__ float g_ctx[Bb*Ss*Hh];           // tf32-rounded
__device__ float g_hsr[Mtot*Hh];            // hs tf32
__device__ float g_wqt[Hh*Hh];              // Wq^T  [N][K] tf32
__device__ float g_wkvt[2*KVHh*HDd*Hh];     // Wkv^T tf32
__device__ float g_wdt[Hh*Hh];              // Wd^T tf32
__device__ float g_cos[Ss*64];
__device__ float g_sin[Ss*64];

// ---------------- helpers ----------------
__device__ __forceinline__ uint32_t smem_u32(const void* p) {
    uint32_t a;
    asm("{ .reg .u64 t; cvta.to.shared.u64 t, %1; cvt.u32.u64 %0, t; }" : "=r"(a) : "l"(p));
    return a;
}
__device__ __forceinline__ float rnd_tf32(float x) {
    uint32_t u;
    asm("cvt.rna.tf32.f32 %0, %1;" : "=r"(u) : "f"(x));
    return __uint_as_float(u);
}
#define CP_ASYNC16(dst_u32, src_ptr) \
    asm volatile("cp.async.cg.shared.global [%0], [%1], 16;" :: "r"(dst_u32), "l"(src_ptr) : "memory")
#define CP_COMMIT() asm volatile("cp.async.commit_group;" ::: "memory")
#define CP_WAIT(n)  asm volatile("cp.async.wait_group %0;" :: "n"(n) : "memory")

__device__ __forceinline__ void mma_tf32_16n8k8(float* c, const uint32_t* a, const uint32_t* b) {
    asm volatile(
        "mma.sync.aligned.m16n8k8.row.col.f32.tf32.tf32.f32 "
        "{%0,%1,%2,%3}, {%4,%5,%6,%7}, {%8,%9}, {%0,%1,%2,%3};"
        : "+f"(c[0]), "+f"(c[1]), "+f"(c[2]), "+f"(c[3])
        : "r"(a[0]), "r"(a[1]), "r"(a[2]), "r"(a[3]), "r"(b[0]), "r"(b[1]));
}

// ---------------------------------------------------------------------------
// RoPE
// ---------------------------------------------------------------------------
__global__ void rope_table_kernel() {
    int idx = blockIdx.x * blockDim.x + threadIdx.x;
    if (idx >= Ss * 64) return;
    int s = idx >> 6, j = idx & 63;
    double invf = exp(-(double)j * (log(10000.0) / 64.0));
    float th = (float)s * (float)invf;
    g_cos[idx] = (float)cos((double)th);
    g_sin[idx] = (float)sin((double)th);
}

// In-place RoPE on q and k; results rounded to tf32 (consumed only by attention MMA)
__global__ void rope_apply_kernel() {
    int idx = blockIdx.x * blockDim.x + threadIdx.x;
    if (idx >= Bb * Ss * (NHh + KVHh) * 64) return;
    int j    = idx & 63;
    int t    = idx >> 6;
    int head = t % (NHh + KVHh);
    int row  = t / (NHh + KVHh);
    int s    = row & (Ss - 1);
    float c  = g_cos[(s << 6) + j];
    float sn = g_sin[(s << 6) + j];
    float* base;
    if (head < NHh) base = g_q  + ((size_t)row * NHh + head) * HDd;
    else            base = g_kv + ((size_t)row * KVHh + (head - NHh)) * (2 * HDd);
    float x1 = base[j], x2 = base[j + 64];
    base[j]      = rnd_tf32(x1 * c - x2 * sn);
    base[j + 64] = rnd_tf32(x2 * c + x1 * sn);
}

// ---------------------------------------------------------------------------
// tf32 rounding copy + transpose+round + V transpose
// ---------------------------------------------------------------------------
__global__ void cvt_rn_kernel(const float* __restrict__ src, float* __restrict__ dst, int n4) {
    int i = blockIdx.x * blockDim.x + threadIdx.x;
    if (i >= n4) return;
    float4 v = ((const float4*)src)[i];
    v.x = rnd_tf32(v.x); v.y = rnd_tf32(v.y); v.z = rnd_tf32(v.z); v.w = rnd_tf32(v.w);
    ((float4*)dst)[i] = v;
}

// src[K][N] row-major -> dst[N][K] row-major, tf32-rounded
__global__ void transpose_rn_kernel(const float* __restrict__ src, float* __restrict__ dst,
                                    int K, int N) {
    __shared__ float t[32][33];
    int k0 = blockIdx.y * 32, n0 = blockIdx.x * 32;
    int tx = threadIdx.x, ty = threadIdx.y;   // 32 x 8
    #pragma unroll
    for (int i = 0; i < 32; i += 8)
        t[ty + i][tx] = src[(size_t)(k0 + ty + i) * N + n0 + tx];
    __syncthreads();
    #pragma unroll
    for (int i = 0; i < 32; i += 8)
        dst[(size_t)(n0 + ty + i) * K + k0 + tx] = rnd_tf32(t[tx][ty + i]);
}

// V (from g_kv) -> g_vt [b][kvh][d][s], tf32-rounded
__global__ void vtrans_kernel() {
    __shared__ float t[32][33];
    int s0 = blockIdx.x * 32, d0 = blockIdx.y * 32;
    int bk = blockIdx.z;                 // b*KVHh + kvh
    int tx = threadIdx.x, ty = threadIdx.y;   // 32 x 8
    const float* src = g_kv + (size_t)(bk >> 3) * Ss * KVHh * 256
                            + (size_t)(bk & 7) * 256 + 128;
    #pragma unroll
    for (int i = 0; i < 32; i += 8)
        t[ty + i][tx] = src[(size_t)(s0 + ty + i) * (KVHh * 256) + d0 + tx];
    __syncthreads();
    float* dst = g_vt + (size_t)bk * HDd * Ss;
    #pragma unroll
    for (int i = 0; i < 32; i += 8)
        dst[(size_t)(d0 + ty + i) * Ss + s0 + tx] = rnd_tf32(t[tx][ty + i]);
}

// ---------------------------------------------------------------------------
// tf32 mma.sync GEMM (unchanged from R4)
// ---------------------------------------------------------------------------
#define BM 128
#define BN 128
#define BK 32
#define STG 3
#define LDT 36
#define TILEF (BM * LDT)
#define GSMEM_BYTES (STG * 2 * TILEF * 4)

__global__ void __launch_bounds__(256) gemm_mma_kernel(
    const float* __restrict__ A, const float* __restrict__ Bt,
    float* __restrict__ C, int N, int K,
    const float* __restrict__ bias, const float* __restrict__ resid)
{
    extern __shared__ float sm[];
    float* As = sm;
    float* Bs = sm + STG * TILEF;
    const uint32_t as_u = smem_u32(As);
    const uint32_t bs_u = smem_u32(Bs);

    const int tid  = threadIdx.x;
    const int bm   = blockIdx.y * BM, bn = blockIdx.x * BN;
    const int warp = tid >> 5, lane = tid & 31;
    const int g    = lane >> 2, t4 = lane & 3;
    const int wm   = (warp & 1) * 64, wn = (warp >> 1) * 32;

    const int NC = K / BK;

    auto load_stage = [&](int s, int c) {
        const float* Aptr = A  + (size_t)bm * K + (size_t)c * BK;
        const float* Bptr = Bt + (size_t)bn * K + (size_t)c * BK;
        #pragma unroll
        for (int i = 0; i < 4; ++i) {
            int idx = tid + i * 256;
            int row = idx >> 3, seg = idx & 7;
            uint32_t so = (uint32_t)((s * TILEF + row * LDT + seg * 4) * 4);
            CP_ASYNC16(as_u + so, Aptr + (size_t)row * K + seg * 4);
            CP_ASYNC16(bs_u + so, Bptr + (size_t)row * K + seg * 4);
        }
    };

    float acc[4][4][4];
    #pragma unroll
    for (int mi = 0; mi < 4; ++mi)
        #pragma unroll
        for (int ni = 0; ni < 4; ++ni)
            #pragma unroll
            for (int r = 0; r < 4; ++r) acc[mi][ni][r] = 0.f;

    #pragma unroll
    for (int s = 0; s < STG - 1; ++s) { load_stage(s, s); CP_COMMIT(); }

    for (int c = 0; c < NC; ++c) {
        CP_WAIT(STG - 2);
        __syncthreads();
        if (c + STG - 1 < NC) load_stage((c + STG - 1) % STG, c + STG - 1);
        CP_COMMIT();

        const float* Ap = As + (c % STG) * TILEF + (wm + g) * LDT;
        const float* Bp = Bs + (c % STG) * TILEF + (wn + g) * LDT;
        #pragma unroll
        for (int ks = 0; ks < 4; ++ks) {
            const int k0 = ks * 8 + t4;
            uint32_t af[4][4], bf[4][2];
            #pragma unroll
            for (int mi = 0; mi < 4; ++mi) {
                const float* p = Ap + mi * 16 * LDT;
                af[mi][0] = __float_as_uint(p[k0]);
                af[mi][1] = __float_as_uint(p[8 * LDT + k0]);
                af[mi][2] = __float_as_uint(p[k0 + 4]);
                af[mi][3] = __float_as_uint(p[8 * LDT + k0 + 4]);
            }
            #pragma unroll
            for (int ni = 0; ni < 4; ++ni) {
                const float* p = Bp + ni * 8 * LDT;
                bf[ni][0] = __float_as_uint(p[k0]);
                bf[ni][1] = __float_as_uint(p[k0 + 4]);
            }
            #pragma unroll
            for (int mi = 0; mi < 4; ++mi)
                #pragma unroll
                for (int ni = 0; ni < 4; ++ni)
                    mma_tf32_16n8k8(acc[mi][ni], af[mi], bf[ni]);
        }
    }

    #pragma unroll
    for (int mi = 0; mi < 4; ++mi) {
        #pragma unroll
        for (int half = 0; half < 2; ++half) {
            int row = bm + wm + mi * 16 + g + half * 8;
            float* crow = C + (size_t)row * N;
            const float* rrow = resid ? resid + (size_t)row * N : nullptr;
            #pragma unroll
            for (int ni = 0; ni < 4; ++ni) {
                int col = bn + wn + ni * 8 + 2 * t4;
                float v0 = acc[mi][ni][half * 2 + 0];
                float v1 = acc[mi][ni][half * 2 + 1];
                if (bias) { v0 += bias[col]; v1 += bias[col + 1]; }
                if (rrow) { v0 += rrow[col]; v1 += rrow[col + 1]; }
                *(float2*)&crow[col] = make_float2(v0, v1);
            }
        }
    }
}

// ---------------------------------------------------------------------------
// Flash attention on tensor cores (tf32 mma.sync)
// CTA = (64-row Q tile, head, batch); 128 threads / 4 warps, 16 Q-rows per warp.
// S = Q K^T via m16n8k8 (K smem [s][d] = natural col-major B),
// O += P V via m16n8k8 (V smem [d][s] from pre-transposed g_vt).
// K/V double-buffered with cp.async.
// ---------------------------------------------------------------------------
#define AT_LQ 132
#define AT_LK 132
#define AT_LV 68
#define AT_LP 72
#define AT_QS  0
#define AT_KS  (64*AT_LQ)                    // 8448
#define AT_VS  (AT_KS + 2*64*AT_LK)          // 8448 + 16896
#define AT_PS  (AT_VS + 2*128*AT_LV)         // + 17408
#define AT_SMEM_FLOATS (AT_PS + 64*AT_LP)
#define AT_SMEM_BYTES  (AT_SMEM_FLOATS * 4)  // 189440

__global__ void __launch_bounds__(128) attn_mma_kernel() {
    extern __shared__ float smf[];
    float* Qs = smf + AT_QS;   // [64][AT_LQ]
    float* Ks = smf + AT_KS;   // [2][64][AT_LK]
    float* Vs = smf + AT_VS;   // [2][128][AT_LV]
    float* Ps = smf + AT_PS;   // [64][AT_LP]
    const uint32_t ks_u = smem_u32(Ks), vs_u = smem_u32(Vs);

    const int tid = threadIdx.x, warp = tid >> 5, lane = tid & 31;
    const int g = lane >> 2, t4 = lane & 3;
    const int qt = blockIdx.x, h = blockIdx.y, b = blockIdx.z;
    const int kvh = h >> 2;
    const float scale = 0.08838834764831845f;   // 1/sqrt(128)

    // Q tile: rows q(64) x d(128), scaled + tf32-rounded
    #pragma unroll
    for (int i = 0; i < 16; ++i) {
        int lin = tid + i * 128;
        int r = lin >> 5, c4 = (lin & 31) << 2;
        float4 v = *(const float4*)(g_q + ((size_t)(b * Ss + qt * 64 + r) * NHh + h) * HDd + c4);
        float* dst = Qs + r * AT_LQ + c4;
        dst[0] = rnd_tf32(v.x * scale); dst[1] = rnd_tf32(v.y * scale);
        dst[2] = rnd_tf32(v.z * scale); dst[3] = rnd_tf32(v.w * scale);
    }

    auto load_kv = [&](int st, int kt) {
        const float* kbase = g_kv + ((size_t)(b * Ss + kt * 64) * KVHh + kvh) * 256;
        #pragma unroll
        for (int i = 0; i < 16; ++i) {   // K: 64 rows x 32 chunks
            int lin = tid + i * 128;
            int r = lin >> 5, c4 = (lin & 31) << 2;
            CP_ASYNC16(ks_u + (uint32_t)((st * 64 * AT_LK + r * AT_LK + c4) * 4),
                       kbase + (size_t)r * (KVHh * 256) + c4);
        }
        const float* vbase = g_vt + (size_t)(b * KVHh + kvh) * HDd * Ss + kt * 64;
        #pragma unroll
        for (int i = 0; i < 16; ++i) {   // V: 128 rows x 16 chunks
            int lin = tid + i * 128;
            int r = lin >> 4, c4 = (lin & 15) << 2;
            CP_ASYNC16(vs_u + (uint32_t)((st * 128 * AT_LV + r * AT_LV + c4) * 4),
                       vbase + (size_t)r * Ss + c4);
        }
    };

    float m_i[2], l_i[2];
    m_i[0] = m_i[1] = -INFINITY;
    l_i[0] = l_i[1] = 0.f;
    float o[16][4];
    #pragma unroll
    for (int ni = 0; ni < 16; ++ni)
        #pragma unroll
        for (int r = 0; r < 4; ++r) o[ni][r] = 0.f;

    load_kv(0, 0); CP_COMMIT();
    __syncthreads();   // Qs written with normal stores; also pre-loop alignment

    const float* Ap = Qs + (16 * warp + g) * AT_LQ;
    const float* Pp = Ps + (16 * warp + g) * AT_LP;

    for (int kt = 0; kt <= qt; ++kt) {
        const int st = kt & 1;
        CP_WAIT(0);
        __syncthreads();
        if (kt < qt) { load_kv(st ^ 1, kt + 1); CP_COMMIT(); }

        // ---- S = Q K^T : 8 n-tiles x 16 k-steps ----
        float c[8][4];
        #pragma unroll
        for (int ni = 0; ni < 8; ++ni)
            #pragma unroll
            for (int r = 0; r < 4; ++r) c[ni][r] = 0.f;

        const float* Bk = Ks + st * 64 * AT_LK;
        #pragma unroll
        for (int ks = 0; ks < 16; ++ks) {
            const int k0 = ks * 8 + t4;
            uint32_t af[4] = { __float_as_uint(Ap[k0]),
                               __float_as_uint(Ap[8 * AT_LQ + k0]),
                               __float_as_uint(Ap[k0 + 4]),
                               __float_as_uint(Ap[8 * AT_LQ + k0 + 4]) };
            #pragma unroll
            for (int ni = 0; ni < 8; ++ni) {
                const float* p = Bk + (ni * 8 + g) * AT_LK;
                uint32_t bf[2] = { __float_as_uint(p[k0]), __float_as_uint(p[k0 + 4]) };
                mma_tf32_16n8k8(c[ni], af, bf);
            }
        }

        // causal mask on diagonal tile
        if (kt == qt) {
            #pragma unroll
            for (int r = 0; r < 2; ++r) {
                const int rloc = 16 * warp + g + 8 * r;
                #pragma unroll
                for (int ni = 0; ni < 8; ++ni) {
                    const int cloc = ni * 8 + 2 * t4;
                    if (cloc     > rloc) c[ni][2 * r]     = -INFINITY;
                    if (cloc + 1 > rloc) c[ni][2 * r + 1] = -INFINITY;
                }
            }
        }

        // ---- online softmax, in-register + quad shuffle ----
        #pragma unroll
        for (int r = 0; r < 2; ++r) {
            float mt = -INFINITY;
            #pragma unroll
            for (int ni = 0; ni < 8; ++ni)
                mt = fmaxf(mt, fmaxf(c[ni][2 * r], c[ni][2 * r + 1]));
            mt = fmaxf(mt, __shfl_xor_sync(0xffffffffu, mt, 1));
            mt = fmaxf(mt, __shfl_xor_sync(0xffffffffu, mt, 2));
            const float mn = fmaxf(m_i[r], mt);
            const float corr = __expf(m_i[r] - mn);
            float rs = 0.f;
            #pragma unroll
            for (int ni = 0; ni < 8; ++ni) {
                float p0 = __expf(c[ni][2 * r]     - mn);
                float p1 = __expf(c[ni][2 * r + 1] - mn);
                rs += p0 + p1;
                *(float2*)&Ps[(16 * warp + g + 8 * r) * AT_LP + ni * 8 + 2 * t4] =
                    make_float2(rnd_tf32(p0), rnd_tf32(p1));
            }
            rs += __shfl_xor_sync(0xffffffffu, rs, 1);
            rs += __shfl_xor_sync(0xffffffffu, rs, 2);
            l_i[r] = l_i[r] * corr + rs;
            m_i[r] = mn;
            #pragma unroll
            for (int ni = 0; ni < 16; ++ni) {
                o[ni][2 * r]     *= corr;
                o[ni][2 * r + 1] *= corr;
            }
        }
        __syncwarp();   // order P stores before P loads (warp-private rows)

        // ---- O += P V : 16 n-tiles x 8 k-steps ----
        const float* Bv = Vs + st * 128 * AT_LV;
        #pragma unroll
        for (int ks = 0; ks < 8; ++ks) {
            const int k0 = ks * 8 + t4;
            uint32_t af[4] = { __float_as_uint(Pp[k0]),
                               __float_as_uint(Pp[8 * AT_LP + k0]),
                               __float_as_uint(Pp[k0 + 4]),
                               __float_as_uint(Pp[8 * AT_LP + k0 + 4]) };
            #pragma unroll
            for (int ni = 0; ni < 16; ++ni) {
                const float* p = Bv + (ni * 8 + g) * AT_LV;
                uint32_t bf[2] = { __float_as_uint(p[k0]), __float_as_uint(p[k0 + 4]) };
                mma_tf32_16n8k8(o[ni], af, bf);
            }
        }
    }

    // ---- normalize + store ctx (tf32-rounded) ----
    #pragma unroll
    for (int r = 0; r < 2; ++r) {
        const float inv = 1.f / l_i[r];
        const int row = qt * 64 + 16 * warp + g + 8 * r;
        float* obase = g_ctx + (size_t)(b * Ss + row) * Hh + h * HDd;
        #pragma unroll
        for (int ni = 0; ni < 16; ++ni) {
            const int col = ni * 8 + 2 * t4;
            *(float2*)&obase[col] = make_float2(rnd_tf32(o[ni][2 * r] * inv),
                                                rnd_tf32(o[ni][2 * r + 1] * inv));
        }
    }
}

// ---------------------------------------------------------------------------
extern "C" void kernel_launch(void* const* d_in, const int* in_sizes, int n_in,
                              void* d_out, int out_size) {
    const float* hs  = (const float*)d_in[0];
    const float* res = (const float*)d_in[1];
    const float* Wq  = (const float*)d_in[3];
    const float* Wkv = (const float*)d_in[4];
    const float* Wd  = (const float*)d_in[5];
    const float* bd  = (const float*)d_in[6];
    float* out = (float*)d_out;

    float *qp, *kvp, *ctxp, *hsr, *wqt, *wkvt, *wdt;
    cudaGetSymbolAddress((void**)&qp,   g_q);
    cudaGetSymbolAddress((void**)&kvp,  g_kv);
    cudaGetSymbolAddress((void**)&ctxp, g_ctx);
    cudaGetSymbolAddress((void**)&hsr,  g_hsr);
    cudaGetSymbolAddress((void**)&wqt,  g_wqt);
    cudaGetSymbolAddress((void**)&wkvt, g_wkvt);
    cudaGetSymbolAddress((void**)&wdt,  g_wdt);

    cudaFuncSetAttribute(attn_mma_kernel, cudaFuncAttributeMaxDynamicSharedMemorySize, AT_SMEM_BYTES);
    cudaFuncSetAttribute(gemm_mma_kernel, cudaFuncAttributeMaxDynamicSharedMemorySize, GSMEM_BYTES);

    const int NKV = 2 * KVHh * HDd;   // 2048

    rope_table_kernel<<<(Ss * 64 + 255) / 256, 256>>>();
    cvt_rn_kernel<<<(Mtot * Hh / 4 + 255) / 256, 256>>>(hs, hsr, Mtot * Hh / 4);
    transpose_rn_kernel<<<dim3(Hh / 32, Hh / 32), dim3(32, 8)>>>(Wq,  wqt,  Hh, Hh);
    transpose_rn_kernel<<<dim3(NKV / 32, Hh / 32), dim3(32, 8)>>>(Wkv, wkvt, Hh, NKV);
    transpose_rn_kernel<<<dim3(Hh / 32, Hh / 32), dim3(32, 8)>>>(Wd,  wdt,  Hh, Hh);

    gemm_mma_kernel<<<dim3(Hh / BN, Mtot / BM), 256, GSMEM_BYTES>>>(hsr, wqt, qp, Hh, Hh, nullptr, nullptr);
    gemm_mma_kernel<<<dim3(NKV / BN, Mtot / BM), 256, GSMEM_BYTES>>>(hsr, wkvt, kvp, NKV, Hh, nullptr, nullptr);

    rope_apply_kernel<<<(Bb * Ss * (NHh + KVHh) * 64 + 255) / 256, 256>>>();
    vtrans_kernel<<<dim3(Ss / 32, HDd / 32, Bb * KVHh), dim3(32, 8)>>>();

    attn_mma_kernel<<<dim3(Ss / 64, NHh, Bb), 128, AT_SMEM_BYTES>>>();

    gemm_mma_kernel<<<dim3(Hh / BN, Mtot / BM), 256, GSMEM_BYTES>>>(ctxp, wdt, out, Hh, Hh, bd, res);
}

// round 6
// speedup vs baseline: 6.3636x; 1.9053x over previous
#include <cuda_runtime.h>
#include <cuda_fp16.h>
#include <math.h>
#include <stdint.h>

#define Bb   2
#define Ss   2048
#define Hh   4096
#define NHh  32
#define HDd  128
#define KVHh 8
#define Mtot (Bb*Ss)          // 4096
#define NQKV 6144             // 4096 q + 2048 kv

// ---------------- scratch (allocation-free) ----------------
__device__ float  g_qkv[Mtot*NQKV];           // fused QKV GEMM output (fp32)
__device__ __half g_hsh[Mtot*Hh];             // hs fp16
__device__ __half g_wt[NQKV*Hh];              // [Wq^T ; Wkv^T] fp16 [N][K]
__device__ __half g_wdt[Hh*Hh];               // Wd^T fp16
__device__ __half g_qh[Bb*Ss*NHh*HDd];        // post-RoPE q, pre-scaled, fp16
__device__ __half g_kh[Bb*Ss*KVHh*HDd];       // post-RoPE k, fp16
__device__ __half g_vt[Bb*KVHh*HDd*Ss];       // V transposed [b][kvh][d][s] fp16
__device__ __half g_ctxh[Mtot*Hh];            // attention output fp16
__device__ float  g_cos[Ss*64];
__device__ float  g_sin[Ss*64];

// ---------------- helpers ----------------
__device__ __forceinline__ uint32_t smem_u32(const void* p) {
    uint32_t a;
    asm("{ .reg .u64 t; cvta.to.shared.u64 t, %1; cvt.u32.u64 %0, t; }" : "=r"(a) : "l"(p));
    return a;
}
#define CP_ASYNC16(dst_u32, src_ptr) \
    asm volatile("cp.async.cg.shared.global [%0], [%1], 16;" :: "r"(dst_u32), "l"(src_ptr) : "memory")
#define CP_COMMIT() asm volatile("cp.async.commit_group;" ::: "memory")
#define CP_WAIT(n)  asm volatile("cp.async.wait_group %0;" :: "n"(n) : "memory")

__device__ __forceinline__ void mma_f16_16n8k16(float* c, const uint32_t* a, const uint32_t* b) {
    asm volatile(
        "mma.sync.aligned.m16n8k16.row.col.f32.f16.f16.f32 "
        "{%0,%1,%2,%3}, {%4,%5,%6,%7}, {%8,%9}, {%0,%1,%2,%3};"
        : "+f"(c[0]), "+f"(c[1]), "+f"(c[2]), "+f"(c[3])
        : "r"(a[0]), "r"(a[1]), "r"(a[2]), "r"(a[3]), "r"(b[0]), "r"(b[1]));
}
__device__ __forceinline__ uint32_t ldh2(const __half* p) {
    return *(const uint32_t*)p;
}

// ---------------------------------------------------------------------------
// RoPE tables
// ---------------------------------------------------------------------------
__global__ void rope_table_kernel() {
    int idx = blockIdx.x * blockDim.x + threadIdx.x;
    if (idx >= Ss * 64) return;
    int s = idx >> 6, j = idx & 63;
    double invf = exp(-(double)j * (log(10000.0) / 64.0));
    float th = (float)s * (float)invf;
    g_cos[idx] = (float)cos((double)th);
    g_sin[idx] = (float)sin((double)th);
}

// RoPE on q (pre-scaled by 1/sqrt(HD)) and k, fp32 in (g_qkv) -> fp16 out
__global__ void rope_apply_kernel() {
    int idx = blockIdx.x * blockDim.x + threadIdx.x;
    if (idx >= Bb * Ss * (NHh + KVHh) * 64) return;
    const float qscale = 0.08838834764831845f;   // 1/sqrt(128)
    int j    = idx & 63;
    int t    = idx >> 6;
    int head = t % (NHh + KVHh);
    int row  = t / (NHh + KVHh);
    int s    = row & (Ss - 1);
    float c  = g_cos[(s << 6) + j];
    float sn = g_sin[(s << 6) + j];
    if (head < NHh) {
        const float* base = g_qkv + (size_t)row * NQKV + head * HDd;
        float x1 = base[j], x2 = base[j + 64];
        __half* dst = g_qh + ((size_t)row * NHh + head) * HDd;
        dst[j]      = __float2half_rn((x1 * c - x2 * sn) * qscale);
        dst[j + 64] = __float2half_rn((x2 * c + x1 * sn) * qscale);
    } else {
        int kvh = head - NHh;
        const float* base = g_qkv + (size_t)row * NQKV + Hh + kvh * 256;
        float x1 = base[j], x2 = base[j + 64];
        __half* dst = g_kh + ((size_t)row * KVHh + kvh) * HDd;
        dst[j]      = __float2half_rn(x1 * c - x2 * sn);
        dst[j + 64] = __float2half_rn(x2 * c + x1 * sn);
    }
}

// ---------------------------------------------------------------------------
// fp16 conversion / transposition preps
// ---------------------------------------------------------------------------
__global__ void cvt_h_kernel(const float* __restrict__ src, __half* __restrict__ dst, int n4) {
    int i = blockIdx.x * blockDim.x + threadIdx.x;
    if (i >= n4) return;
    float4 v = ((const float4*)src)[i];
    __half2* d2 = (__half2*)dst;
    d2[i * 2]     = __floats2half2_rn(v.x, v.y);
    d2[i * 2 + 1] = __floats2half2_rn(v.z, v.w);
}

// src[K][N] fp32 row-major -> dst[N][K] fp16 row-major
__global__ void transpose_h_kernel(const float* __restrict__ src, __half* __restrict__ dst,
                                   int K, int N) {
    __shared__ float t[32][33];
    int k0 = blockIdx.y * 32, n0 = blockIdx.x * 32;
    int tx = threadIdx.x, ty = threadIdx.y;   // 32 x 8
    #pragma unroll
    for (int i = 0; i < 32; i += 8)
        t[ty + i][tx] = src[(size_t)(k0 + ty + i) * N + n0 + tx];
    __syncthreads();
    #pragma unroll
    for (int i = 0; i < 32; i += 8)
        dst[(size_t)(n0 + ty + i) * K + k0 + tx] = __float2half_rn(t[tx][ty + i]);
}

// V (fp32, inside g_qkv) -> g_vt fp16 [b][kvh][d][s]
__global__ void vtrans_kernel() {
    __shared__ float t[32][33];
    int s0 = blockIdx.x * 32, d0 = blockIdx.y * 32;
    int bk = blockIdx.z;                 // b*KVHh + kvh
    int b = bk >> 3, kvh = bk & 7;
    int tx = threadIdx.x, ty = threadIdx.y;   // 32 x 8
    const float* src = g_qkv + (size_t)(b * Ss) * NQKV + Hh + kvh * 256 + 128;
    #pragma unroll
    for (int i = 0; i < 32; i += 8)
        t[ty + i][tx] = src[(size_t)(s0 + ty + i) * NQKV + d0 + tx];
    __syncthreads();
    __half* dst = g_vt + (size_t)bk * HDd * Ss;
    #pragma unroll
    for (int i = 0; i < 32; i += 8)
        dst[(size_t)(d0 + ty + i) * Ss + s0 + tx] = __float2half_rn(t[tx][ty + i]);
}

// ---------------------------------------------------------------------------
// fp16 mma.sync GEMM:  C[M,N](fp32) = A[M,K] @ B^T  (A,Bt fp16; Bt=[N][K])
// CTA 128x128, BK=64, 3-stage cp.async, 8 warps, warp tile 64x32,
// m16n8k16, padded stride 72 halves (conflict-free half2 gathers).
// ---------------------------------------------------------------------------
#define BM 128
#define BN 128
#define BK 64
#define STG 3
#define LDT 72
#define TILEH (BM * LDT)                  // halves per tile per stage
#define GSMEM_BYTES (STG * 2 * TILEH * 2) // 110592

__global__ void __launch_bounds__(256) gemm_f16_kernel(
    const __half* __restrict__ A, const __half* __restrict__ Bt,
    float* __restrict__ C, int N, int K,
    const float* __restrict__ bias, const float* __restrict__ resid)
{
    extern __shared__ __half smh[];
    __half* As = smh;                 // [STG][BM][LDT]
    __half* Bs = smh + STG * TILEH;   // [STG][BN][LDT]
    const uint32_t as_u = smem_u32(As);
    const uint32_t bs_u = smem_u32(Bs);

    const int tid  = threadIdx.x;
    const int bm   = blockIdx.y * BM, bn = blockIdx.x * BN;
    const int warp = tid >> 5, lane = tid & 31;
    const int g    = lane >> 2, t4 = lane & 3;
    const int wm   = (warp & 1) * 64, wn = (warp >> 1) * 32;

    const int NC = K / BK;

    auto load_stage = [&](int s, int c) {
        const __half* Aptr = A  + (size_t)bm * K + (size_t)c * BK;
        const __half* Bptr = Bt + (size_t)bn * K + (size_t)c * BK;
        #pragma unroll
        for (int i = 0; i < 4; ++i) {
            int idx = tid + i * 256;
            int row = idx >> 3, c8 = idx & 7;
            uint32_t so = (uint32_t)((s * TILEH + row * LDT + c8 * 8) * 2);
            CP_ASYNC16(as_u + so, Aptr + (size_t)row * K + c8 * 8);
            CP_ASYNC16(bs_u + so, Bptr + (size_t)row * K + c8 * 8);
        }
    };

    float acc[4][4][4];
    #pragma unroll
    for (int mi = 0; mi < 4; ++mi)
        #pragma unroll
        for (int ni = 0; ni < 4; ++ni)
            #pragma unroll
            for (int r = 0; r < 4; ++r) acc[mi][ni][r] = 0.f;

    #pragma unroll
    for (int s = 0; s < STG - 1; ++s) { load_stage(s, s); CP_COMMIT(); }

    for (int c = 0; c < NC; ++c) {
        CP_WAIT(STG - 2);
        __syncthreads();
        if (c + STG - 1 < NC) load_stage((c + STG - 1) % STG, c + STG - 1);
        CP_COMMIT();

        const __half* Ap = As + (c % STG) * TILEH + (wm + g) * LDT;
        const __half* Bp = Bs + (c % STG) * TILEH + (wn + g) * LDT;
        #pragma unroll
        for (int ks = 0; ks < 4; ++ks) {
            const int k0 = ks * 16 + 2 * t4;
            uint32_t af[4][4], bf[4][2];
            #pragma unroll
            for (int mi = 0; mi < 4; ++mi) {
                const __half* p = Ap + mi * 16 * LDT;
                af[mi][0] = ldh2(p + k0);
                af[mi][1] = ldh2(p + 8 * LDT + k0);
                af[mi][2] = ldh2(p + k0 + 8);
                af[mi][3] = ldh2(p + 8 * LDT + k0 + 8);
            }
            #pragma unroll
            for (int ni = 0; ni < 4; ++ni) {
                const __half* p = Bp + ni * 8 * LDT;
                bf[ni][0] = ldh2(p + k0);
                bf[ni][1] = ldh2(p + k0 + 8);
            }
            #pragma unroll
            for (int mi = 0; mi < 4; ++mi)
                #pragma unroll
                for (int ni = 0; ni < 4; ++ni)
                    mma_f16_16n8k16(acc[mi][ni], af[mi], bf[ni]);
        }
    }

    #pragma unroll
    for (int mi = 0; mi < 4; ++mi) {
        #pragma unroll
        for (int half = 0; half < 2; ++half) {
            int row = bm + wm + mi * 16 + g + half * 8;
            float* crow = C + (size_t)row * N;
            const float* rrow = resid ? resid + (size_t)row * N : nullptr;
            #pragma unroll
            for (int ni = 0; ni < 4; ++ni) {
                int col = bn + wn + ni * 8 + 2 * t4;
                float v0 = acc[mi][ni][half * 2 + 0];
                float v1 = acc[mi][ni][half * 2 + 1];
                if (bias) { v0 += bias[col]; v1 += bias[col + 1]; }
                if (rrow) { v0 += rrow[col]; v1 += rrow[col + 1]; }
                *(float2*)&crow[col] = make_float2(v0, v1);
            }
        }
    }
}

// ---------------------------------------------------------------------------
// Flash attention, fp16 mma.sync (m16n8k16)
// CTA = (64-row Q tile, head, batch); 128 threads / 4 warps, 16 Q rows/warp.
// Strides: Q/K rows 136 halves, V/P rows 72 halves (conflict-free).
// K/V double-buffered cp.async; ~96KB smem -> 2 CTAs/SM.
// ---------------------------------------------------------------------------
#define AT_LQ 136
#define AT_LV 72
#define AT_QS  0
#define AT_KS  (64*AT_LQ)                       // 8704
#define AT_VS  (AT_KS + 2*64*AT_LQ)             // + 17408
#define AT_PS  (AT_VS + 2*128*AT_LV)            // + 18432
#define AT_SMEM_HALVES (AT_PS + 64*AT_LV)
#define AT_SMEM_BYTES  (AT_SMEM_HALVES * 2)     // 98304

__global__ void __launch_bounds__(128) attn_f16_kernel() {
    extern __shared__ __half smh[];
    __half* Qs = smh + AT_QS;   // [64][136]
    __half* Ks = smh + AT_KS;   // [2][64][136]
    __half* Vs = smh + AT_VS;   // [2][128][72]
    __half* Ps = smh + AT_PS;   // [64][72]
    const uint32_t qs_u = smem_u32(Qs), ks_u = smem_u32(Ks), vs_u = smem_u32(Vs);

    const int tid = threadIdx.x, warp = tid >> 5, lane = tid & 31;
    const int g = lane >> 2, t4 = lane & 3;
    const int qt = blockIdx.x, h = blockIdx.y, b = blockIdx.z;
    const int kvh = h >> 2;

    // Q tile (pre-scaled fp16): 64 rows x 128 halves via cp.async
    {
        const __half* qbase = g_qh + ((size_t)(b * Ss + qt * 64) * NHh + h) * HDd;
        #pragma unroll
        for (int i = 0; i < 8; ++i) {
            int lin = tid + i * 128;
            int r = lin >> 4, c8 = (lin & 15) << 3;
            CP_ASYNC16(qs_u + (uint32_t)((r * AT_LQ + c8) * 2),
                       qbase + (size_t)r * (NHh * HDd) + c8);
        }
    }

    auto load_kv = [&](int st, int kt) {
        const __half* kbase = g_kh + ((size_t)(b * Ss + kt * 64) * KVHh + kvh) * HDd;
        #pragma unroll
        for (int i = 0; i < 8; ++i) {
            int lin = tid + i * 128;
            int r = lin >> 4, c8 = (lin & 15) << 3;
            CP_ASYNC16(ks_u + (uint32_t)((st * 64 * AT_LQ + r * AT_LQ + c8) * 2),
                       kbase + (size_t)r * (KVHh * HDd) + c8);
        }
        const __half* vbase = g_vt + (size_t)(b * KVHh + kvh) * HDd * Ss + kt * 64;
        #pragma unroll
        for (int i = 0; i < 8; ++i) {
            int lin = tid + i * 128;
            int r = lin >> 3, c8 = (lin & 7) << 3;
            CP_ASYNC16(vs_u + (uint32_t)((st * 128 * AT_LV + r * AT_LV + c8) * 2),
                       vbase + (size_t)r * Ss + c8);
        }
    };

    float m_i[2], l_i[2];
    m_i[0] = m_i[1] = -INFINITY;
    l_i[0] = l_i[1] = 0.f;
    float o[16][4];
    #pragma unroll
    for (int ni = 0; ni < 16; ++ni)
        #pragma unroll
        for (int r = 0; r < 4; ++r) o[ni][r] = 0.f;

    load_kv(0, 0); CP_COMMIT();

    const __half* Ap = Qs + (16 * warp + g) * AT_LQ;
    const __half* Pp = Ps + (16 * warp + g) * AT_LV;

    for (int kt = 0; kt <= qt; ++kt) {
        const int st = kt & 1;
        CP_WAIT(0);
        __syncthreads();
        if (kt < qt) { load_kv(st ^ 1, kt + 1); CP_COMMIT(); }

        // ---- S = Q K^T : 8 n-tiles x 8 k-steps ----
        float c[8][4];
        #pragma unroll
        for (int ni = 0; ni < 8; ++ni)
            #pragma unroll
            for (int r = 0; r < 4; ++r) c[ni][r] = 0.f;

        const __half* Bk = Ks + st * 64 * AT_LQ;
        #pragma unroll
        for (int ks = 0; ks < 8; ++ks) {
            const int k0 = ks * 16 + 2 * t4;
            uint32_t af[4] = { ldh2(Ap + k0), ldh2(Ap + 8 * AT_LQ + k0),
                               ldh2(Ap + k0 + 8), ldh2(Ap + 8 * AT_LQ + k0 + 8) };
            #pragma unroll
            for (int ni = 0; ni < 8; ++ni) {
                const __half* p = Bk + (ni * 8 + g) * AT_LQ;
                uint32_t bf[2] = { ldh2(p + k0), ldh2(p + k0 + 8) };
                mma_f16_16n8k16(c[ni], af, bf);
            }
        }

        if (kt == qt) {   // causal mask on diagonal tile
            #pragma unroll
            for (int r = 0; r < 2; ++r) {
                const int rloc = 16 * warp + g + 8 * r;
                #pragma unroll
                for (int ni = 0; ni < 8; ++ni) {
                    const int cloc = ni * 8 + 2 * t4;
                    if (cloc     > rloc) c[ni][2 * r]     = -INFINITY;
                    if (cloc + 1 > rloc) c[ni][2 * r + 1] = -INFINITY;
                }
            }
        }

        // ---- online softmax (fp32, in-register + quad shuffle) ----
        #pragma unroll
        for (int r = 0; r < 2; ++r) {
            float mt = -INFINITY;
            #pragma unroll
            for (int ni = 0; ni < 8; ++ni)
                mt = fmaxf(mt, fmaxf(c[ni][2 * r], c[ni][2 * r + 1]));
            mt = fmaxf(mt, __shfl_xor_sync(0xffffffffu, mt, 1));
            mt = fmaxf(mt, __shfl_xor_sync(0xffffffffu, mt, 2));
            const float mn = fmaxf(m_i[r], mt);
            const float corr = __expf(m_i[r] - mn);
            float rs = 0.f;
            #pragma unroll
            for (int ni = 0; ni < 8; ++ni) {
                float p0 = __expf(c[ni][2 * r]     - mn);
                float p1 = __expf(c[ni][2 * r + 1] - mn);
                rs += p0 + p1;
                *(__half2*)&Ps[(16 * warp + g + 8 * r) * AT_LV + ni * 8 + 2 * t4] =
                    __floats2half2_rn(p0, p1);
            }
            rs += __shfl_xor_sync(0xffffffffu, rs, 1);
            rs += __shfl_xor_sync(0xffffffffu, rs, 2);
            l_i[r] = l_i[r] * corr + rs;
            m_i[r] = mn;
            #pragma unroll
            for (int ni = 0; ni < 16; ++ni) {
                o[ni][2 * r]     *= corr;
                o[ni][2 * r + 1] *= corr;
            }
        }
        __syncwarp();   // P rows are warp-private: order stores before loads

        // ---- O += P V : 16 n-tiles x 4 k-steps ----
        const __half* Bv = Vs + st * 128 * AT_LV;
        #pragma unroll
        for (int ks = 0; ks < 4; ++ks) {
            const int k0 = ks * 16 + 2 * t4;
            uint32_t af[4] = { ldh2(Pp + k0), ldh2(Pp + 8 * AT_LV + k0),
                               ldh2(Pp + k0 + 8), ldh2(Pp + 8 * AT_LV + k0 + 8) };
            #pragma unroll
            for (int ni = 0; ni < 16; ++ni) {
                const __half* p = Bv + (ni * 8 + g) * AT_LV;
                uint32_t bf[2] = { ldh2(p + k0), ldh2(p + k0 + 8) };
                mma_f16_16n8k16(o[ni], af, bf);
            }
        }
    }

    // ---- normalize + store ctx (fp16) ----
    #pragma unroll
    for (int r = 0; r < 2; ++r) {
        const float inv = 1.f / l_i[r];
        const int row = qt * 64 + 16 * warp + g + 8 * r;
        __half* obase = g_ctxh + (size_t)(b * Ss + row) * Hh + h * HDd;
        #pragma unroll
        for (int ni = 0; ni < 16; ++ni) {
            const int col = ni * 8 + 2 * t4;
            *(__half2*)&obase[col] = __floats2half2_rn(o[ni][2 * r] * inv,
                                                       o[ni][2 * r + 1] * inv);
        }
    }
}

// ---------------------------------------------------------------------------
extern "C" void kernel_launch(void* const* d_in, const int* in_sizes, int n_in,
                              void* d_out, int out_size) {
    const float* hs  = (const float*)d_in[0];
    const float* res = (const float*)d_in[1];
    const float* Wq  = (const float*)d_in[3];
    const float* Wkv = (const float*)d_in[4];
    const float* Wd  = (const float*)d_in[5];
    const float* bd  = (const float*)d_in[6];
    float* out = (float*)d_out;

    float* qkvp;
    __half *hsh, *wt, *wdt, *ctxh;
    cudaGetSymbolAddress((void**)&qkvp, g_qkv);
    cudaGetSymbolAddress((void**)&hsh,  g_hsh);
    cudaGetSymbolAddress((void**)&wt,   g_wt);
    cudaGetSymbolAddress((void**)&wdt,  g_wdt);
    cudaGetSymbolAddress((void**)&ctxh, g_ctxh);

    cudaFuncSetAttribute(attn_f16_kernel, cudaFuncAttributeMaxDynamicSharedMemorySize, AT_SMEM_BYTES);
    cudaFuncSetAttribute(gemm_f16_kernel, cudaFuncAttributeMaxDynamicSharedMemorySize, GSMEM_BYTES);

    const int NKV = 2 * KVHh * HDd;   // 2048

    rope_table_kernel<<<(Ss * 64 + 255) / 256, 256>>>();
    cvt_h_kernel<<<(Mtot * Hh / 4 + 255) / 256, 256>>>(hs, hsh, Mtot * Hh / 4);
    transpose_h_kernel<<<dim3(Hh / 32, Hh / 32), dim3(32, 8)>>>(Wq,  wt,            Hh, Hh);
    transpose_h_kernel<<<dim3(NKV / 32, Hh / 32), dim3(32, 8)>>>(Wkv, wt + (size_t)Hh * Hh, Hh, NKV);
    transpose_h_kernel<<<dim3(Hh / 32, Hh / 32), dim3(32, 8)>>>(Wd,  wdt,           Hh, Hh);

    // fused QKV projection: C[4096][6144]
    gemm_f16_kernel<<<dim3(NQKV / BN, Mtot / BM), 256, GSMEM_BYTES>>>(
        hsh, wt, qkvp, NQKV, Hh, nullptr, nullptr);

    rope_apply_kernel<<<(Bb * Ss * (NHh + KVHh) * 64 + 255) / 256, 256>>>();
    vtrans_kernel<<<dim3(Ss / 32, HDd / 32, Bb * KVHh), dim3(32, 8)>>>();

    attn_f16_kernel<<<dim3(Ss / 64, NHh, Bb), 128, AT_SMEM_BYTES>>>();

    gemm_f16_kernel<<<dim3(Hh / BN, Mtot / BM), 256, GSMEM_BYTES>>>(
        ctxh, wdt, out, Hh, Hh, bd, res);
}

// round 7
// speedup vs baseline: 7.6484x; 1.2019x over previous
#include <cuda_runtime.h>
#include <cuda_fp16.h>
#include <math.h>
#include <stdint.h>

#define Bb   2
#define Ss   2048
#define Hh   4096
#define NHh  32
#define HDd  128
#define KVHh 8
#define Mtot (Bb*Ss)          // 4096
#define NQKV 6144             // 4096 q + 2048 kv

// ---------------- scratch (allocation-free) ----------------
__device__ float  g_qkv[Mtot*NQKV];           // fused QKV GEMM output (fp32)
__device__ __half g_hsh[Mtot*Hh];             // hs fp16
__device__ __half g_wt[NQKV*Hh];              // [Wq^T ; Wkv^T] fp16 [N][K]
__device__ __half g_wdt[Hh*Hh];               // Wd^T fp16
__device__ __half g_qh[Bb*Ss*NHh*HDd];        // post-RoPE q, pre-scaled, fp16
__device__ __half g_kh[Bb*Ss*KVHh*HDd];       // post-RoPE k, fp16
__device__ __half g_vt[Bb*KVHh*HDd*Ss];       // V transposed [b][kvh][d][s] fp16
__device__ __half g_ctxh[Mtot*Hh];            // attention output fp16
__device__ float  g_cos[Ss*64];
__device__ float  g_sin[Ss*64];

// ---------------- helpers ----------------
__device__ __forceinline__ uint32_t smem_u32(const void* p) {
    uint32_t a;
    asm("{ .reg .u64 t; cvta.to.shared.u64 t, %1; cvt.u32.u64 %0, t; }" : "=r"(a) : "l"(p));
    return a;
}
#define CP_ASYNC16(dst_u32, src_ptr) \
    asm volatile("cp.async.cg.shared.global [%0], [%1], 16;" :: "r"(dst_u32), "l"(src_ptr) : "memory")
#define CP_COMMIT() asm volatile("cp.async.commit_group;" ::: "memory")
#define CP_WAIT(n)  asm volatile("cp.async.wait_group %0;" :: "n"(n) : "memory")

#define LDSM4(r0, r1, r2, r3, addr) \
    asm volatile("ldmatrix.sync.aligned.m8n8.x4.shared.b16 {%0,%1,%2,%3}, [%4];" \
                 : "=r"(r0), "=r"(r1), "=r"(r2), "=r"(r3) : "r"(addr))

__device__ __forceinline__ void mma_f16_16n8k16(float* c, const uint32_t* a, const uint32_t* b) {
    asm volatile(
        "mma.sync.aligned.m16n8k16.row.col.f32.f16.f16.f32 "
        "{%0,%1,%2,%3}, {%4,%5,%6,%7}, {%8,%9}, {%0,%1,%2,%3};"
        : "+f"(c[0]), "+f"(c[1]), "+f"(c[2]), "+f"(c[3])
        : "r"(a[0]), "r"(a[1]), "r"(a[2]), "r"(a[3]), "r"(b[0]), "r"(b[1]));
}

// ---------------------------------------------------------------------------
// RoPE tables
// ---------------------------------------------------------------------------
__global__ void rope_table_kernel() {
    int idx = blockIdx.x * blockDim.x + threadIdx.x;
    if (idx >= Ss * 64) return;
    int s = idx >> 6, j = idx & 63;
    double invf = exp(-(double)j * (log(10000.0) / 64.0));
    float th = (float)s * (float)invf;
    g_cos[idx] = (float)cos((double)th);
    g_sin[idx] = (float)sin((double)th);
}

// RoPE on q (pre-scaled by 1/sqrt(HD)) and k, fp32 in (g_qkv) -> fp16 out
__global__ void rope_apply_kernel() {
    int idx = blockIdx.x * blockDim.x + threadIdx.x;
    if (idx >= Bb * Ss * (NHh + KVHh) * 64) return;
    const float qscale = 0.08838834764831845f;   // 1/sqrt(128)
    int j    = idx & 63;
    int t    = idx >> 6;
    int head = t % (NHh + KVHh);
    int row  = t / (NHh + KVHh);
    int s    = row & (Ss - 1);
    float c  = g_cos[(s << 6) + j];
    float sn = g_sin[(s << 6) + j];
    if (head < NHh) {
        const float* base = g_qkv + (size_t)row * NQKV + head * HDd;
        float x1 = base[j], x2 = base[j + 64];
        __half* dst = g_qh + ((size_t)row * NHh + head) * HDd;
        dst[j]      = __float2half_rn((x1 * c - x2 * sn) * qscale);
        dst[j + 64] = __float2half_rn((x2 * c + x1 * sn) * qscale);
    } else {
        int kvh = head - NHh;
        const float* base = g_qkv + (size_t)row * NQKV + Hh + kvh * 256;
        float x1 = base[j], x2 = base[j + 64];
        __half* dst = g_kh + ((size_t)row * KVHh + kvh) * HDd;
        dst[j]      = __float2half_rn(x1 * c - x2 * sn);
        dst[j + 64] = __float2half_rn(x2 * c + x1 * sn);
    }
}

// ---------------------------------------------------------------------------
// fp16 conversion / transposition preps
// ---------------------------------------------------------------------------
__global__ void cvt_h_kernel(const float* __restrict__ src, __half* __restrict__ dst, int n4) {
    int i = blockIdx.x * blockDim.x + threadIdx.x;
    if (i >= n4) return;
    float4 v = ((const float4*)src)[i];
    __half2* d2 = (__half2*)dst;
    d2[i * 2]     = __floats2half2_rn(v.x, v.y);
    d2[i * 2 + 1] = __floats2half2_rn(v.z, v.w);
}

// src[K][N] fp32 row-major -> dst[N][K] fp16 row-major
__global__ void transpose_h_kernel(const float* __restrict__ src, __half* __restrict__ dst,
                                   int K, int N) {
    __shared__ float t[32][33];
    int k0 = blockIdx.y * 32, n0 = blockIdx.x * 32;
    int tx = threadIdx.x, ty = threadIdx.y;   // 32 x 8
    #pragma unroll
    for (int i = 0; i < 32; i += 8)
        t[ty + i][tx] = src[(size_t)(k0 + ty + i) * N + n0 + tx];
    __syncthreads();
    #pragma unroll
    for (int i = 0; i < 32; i += 8)
        dst[(size_t)(n0 + ty + i) * K + k0 + tx] = __float2half_rn(t[tx][ty + i]);
}

// V (fp32, inside g_qkv) -> g_vt fp16 [b][kvh][d][s]
__global__ void vtrans_kernel() {
    __shared__ float t[32][33];
    int s0 = blockIdx.x * 32, d0 = blockIdx.y * 32;
    int bk = blockIdx.z;                 // b*KVHh + kvh
    int b = bk >> 3, kvh = bk & 7;
    int tx = threadIdx.x, ty = threadIdx.y;   // 32 x 8
    const float* src = g_qkv + (size_t)(b * Ss) * NQKV + Hh + kvh * 256 + 128;
    #pragma unroll
    for (int i = 0; i < 32; i += 8)
        t[ty + i][tx] = src[(size_t)(s0 + ty + i) * NQKV + d0 + tx];
    __syncthreads();
    __half* dst = g_vt + (size_t)bk * HDd * Ss;
    #pragma unroll
    for (int i = 0; i < 32; i += 8)
        dst[(size_t)(d0 + ty + i) * Ss + s0 + tx] = __float2half_rn(t[tx][ty + i]);
}

// ---------------------------------------------------------------------------
// fp16 mma.sync GEMM with ldmatrix fragment loads.
// CTA 128x128, BK=64, 3-stage cp.async, 8 warps, warp tile 64x32.
// Stride 72 halves (144B): rows shift 4 banks -> ldmatrix conflict-free.
// ---------------------------------------------------------------------------
#define BM 128
#define BN 128
#define BK 64
#define STG 3
#define LDT 72
#define TILEH (BM * LDT)                  // halves per tile per stage
#define GSMEM_BYTES (STG * 2 * TILEH * 2) // 110592

__global__ void __launch_bounds__(256) gemm_f16_kernel(
    const __half* __restrict__ A, const __half* __restrict__ Bt,
    float* __restrict__ C, int N, int K,
    const float* __restrict__ bias, const float* __restrict__ resid)
{
    extern __shared__ __half smh[];
    __half* As = smh;                 // [STG][BM][LDT]
    __half* Bs = smh + STG * TILEH;   // [STG][BN][LDT]
    const uint32_t as_u = smem_u32(As);
    const uint32_t bs_u = smem_u32(Bs);

    const int tid  = threadIdx.x;
    const int bm   = blockIdx.y * BM, bn = blockIdx.x * BN;
    const int warp = tid >> 5, lane = tid & 31;
    const int g    = lane >> 2, t4 = lane & 3;
    const int wm   = (warp & 1) * 64, wn = (warp >> 1) * 32;

    // ldmatrix per-thread row/column assignment
    const int a_row = (lane & 7) + 8 * ((lane >> 3) & 1);   // A x4: m-rows, col16 = lane>>4
    const int a_c8  = (lane >> 4) * 8;
    const int b_row = (lane & 7) + 8 * (lane >> 4);         // B x4: n-rows, col16 = (lane>>3)&1
    const int b_c8  = ((lane >> 3) & 1) * 8;

    const int NC = K / BK;

    auto load_stage = [&](int s, int c) {
        const __half* Aptr = A  + (size_t)bm * K + (size_t)c * BK;
        const __half* Bptr = Bt + (size_t)bn * K + (size_t)c * BK;
        #pragma unroll
        for (int i = 0; i < 4; ++i) {
            int idx = tid + i * 256;
            int row = idx >> 3, c8 = idx & 7;
            uint32_t so = (uint32_t)((s * TILEH + row * LDT + c8 * 8) * 2);
            CP_ASYNC16(as_u + so, Aptr + (size_t)row * K + c8 * 8);
            CP_ASYNC16(bs_u + so, Bptr + (size_t)row * K + c8 * 8);
        }
    };

    float acc[4][4][4];
    #pragma unroll
    for (int mi = 0; mi < 4; ++mi)
        #pragma unroll
        for (int ni = 0; ni < 4; ++ni)
            #pragma unroll
            for (int r = 0; r < 4; ++r) acc[mi][ni][r] = 0.f;

    #pragma unroll
    for (int s = 0; s < STG - 1; ++s) { load_stage(s, s); CP_COMMIT(); }

    for (int c = 0; c < NC; ++c) {
        CP_WAIT(STG - 2);
        __syncthreads();
        if (c + STG - 1 < NC) load_stage((c + STG - 1) % STG, c + STG - 1);
        CP_COMMIT();

        const uint32_t a_base = as_u +
            (uint32_t)(((c % STG) * TILEH + (wm + a_row) * LDT + a_c8) * 2);
        const uint32_t b_base = bs_u +
            (uint32_t)(((c % STG) * TILEH + (wn + b_row) * LDT + b_c8) * 2);

        #pragma unroll
        for (int ks = 0; ks < 4; ++ks) {
            uint32_t af[4][4], bf[4][2];
            #pragma unroll
            for (int mi = 0; mi < 4; ++mi)
                LDSM4(af[mi][0], af[mi][1], af[mi][2], af[mi][3],
                      a_base + (uint32_t)(mi * 16 * LDT * 2 + ks * 32));
            #pragma unroll
            for (int nj = 0; nj < 2; ++nj)
                LDSM4(bf[2 * nj][0], bf[2 * nj][1], bf[2 * nj + 1][0], bf[2 * nj + 1][1],
                      b_base + (uint32_t)(nj * 16 * LDT * 2 + ks * 32));
            #pragma unroll
            for (int mi = 0; mi < 4; ++mi)
                #pragma unroll
                for (int ni = 0; ni < 4; ++ni)
                    mma_f16_16n8k16(acc[mi][ni], af[mi], bf[ni]);
        }
    }

    #pragma unroll
    for (int mi = 0; mi < 4; ++mi) {
        #pragma unroll
        for (int half = 0; half < 2; ++half) {
            int row = bm + wm + mi * 16 + g + half * 8;
            float* crow = C + (size_t)row * N;
            const float* rrow = resid ? resid + (size_t)row * N : nullptr;
            #pragma unroll
            for (int ni = 0; ni < 4; ++ni) {
                int col = bn + wn + ni * 8 + 2 * t4;
                float v0 = acc[mi][ni][half * 2 + 0];
                float v1 = acc[mi][ni][half * 2 + 1];
                if (bias) { v0 += bias[col]; v1 += bias[col + 1]; }
                if (rrow) { v0 += rrow[col]; v1 += rrow[col + 1]; }
                *(float2*)&crow[col] = make_float2(v0, v1);
            }
        }
    }
}

// ---------------------------------------------------------------------------
// Flash attention, fp16 mma.sync + ldmatrix
// CTA = (64-row Q tile, head, batch); 128 threads / 4 warps, 16 Q rows/warp.
// Strides: Q/K rows 136 halves (272B), V/P rows 72 halves (144B) -> both
// give 4-bank row shifts: ldmatrix conflict-free.
// ---------------------------------------------------------------------------
#define AT_LQ 136
#define AT_LV 72
#define AT_QS  0
#define AT_KS  (64*AT_LQ)                       // 8704
#define AT_VS  (AT_KS + 2*64*AT_LQ)             // + 17408
#define AT_PS  (AT_VS + 2*128*AT_LV)            // + 18432
#define AT_SMEM_HALVES (AT_PS + 64*AT_LV)
#define AT_SMEM_BYTES  (AT_SMEM_HALVES * 2)     // 98304

__global__ void __launch_bounds__(128) attn_f16_kernel() {
    extern __shared__ __half smh[];
    __half* Qs = smh + AT_QS;   // [64][136]
    __half* Ks = smh + AT_KS;   // [2][64][136]
    __half* Vs = smh + AT_VS;   // [2][128][72]
    __half* Ps = smh + AT_PS;   // [64][72]
    const uint32_t qs_u = smem_u32(Qs), ks_u = smem_u32(Ks), vs_u = smem_u32(Vs);
    const uint32_t ps_u = smem_u32(Ps);

    const int tid = threadIdx.x, warp = tid >> 5, lane = tid & 31;
    const int g = lane >> 2, t4 = lane & 3;
    const int qt = blockIdx.x, h = blockIdx.y, b = blockIdx.z;
    const int kvh = h >> 2;

    const int a_row = (lane & 7) + 8 * ((lane >> 3) & 1);
    const int a_c8  = (lane >> 4) * 8;
    const int b_row = (lane & 7) + 8 * (lane >> 4);
    const int b_c8  = ((lane >> 3) & 1) * 8;

    // Q tile (pre-scaled fp16): 64 rows x 128 halves via cp.async
    {
        const __half* qbase = g_qh + ((size_t)(b * Ss + qt * 64) * NHh + h) * HDd;
        #pragma unroll
        for (int i = 0; i < 8; ++i) {
            int lin = tid + i * 128;
            int r = lin >> 4, c8 = (lin & 15) << 3;
            CP_ASYNC16(qs_u + (uint32_t)((r * AT_LQ + c8) * 2),
                       qbase + (size_t)r * (NHh * HDd) + c8);
        }
    }

    auto load_kv = [&](int st, int kt) {
        const __half* kbase = g_kh + ((size_t)(b * Ss + kt * 64) * KVHh + kvh) * HDd;
        #pragma unroll
        for (int i = 0; i < 8; ++i) {
            int lin = tid + i * 128;
            int r = lin >> 4, c8 = (lin & 15) << 3;
            CP_ASYNC16(ks_u + (uint32_t)((st * 64 * AT_LQ + r * AT_LQ + c8) * 2),
                       kbase + (size_t)r * (KVHh * HDd) + c8);
        }
        const __half* vbase = g_vt + (size_t)(b * KVHh + kvh) * HDd * Ss + kt * 64;
        #pragma unroll
        for (int i = 0; i < 8; ++i) {
            int lin = tid + i * 128;
            int r = lin >> 3, c8 = (lin & 7) << 3;
            CP_ASYNC16(vs_u + (uint32_t)((st * 128 * AT_LV + r * AT_LV + c8) * 2),
                       vbase + (size_t)r * Ss + c8);
        }
    };

    float m_i[2], l_i[2];
    m_i[0] = m_i[1] = -INFINITY;
    l_i[0] = l_i[1] = 0.f;
    float o[16][4];
    #pragma unroll
    for (int ni = 0; ni < 16; ++ni)
        #pragma unroll
        for (int r = 0; r < 4; ++r) o[ni][r] = 0.f;

    load_kv(0, 0); CP_COMMIT();

    const uint32_t qa_base = qs_u +
        (uint32_t)(((16 * warp + a_row) * AT_LQ + a_c8) * 2);
    const uint32_t pa_base = ps_u +
        (uint32_t)(((16 * warp + a_row) * AT_LV + a_c8) * 2);

    for (int kt = 0; kt <= qt; ++kt) {
        const int st = kt & 1;
        CP_WAIT(0);
        __syncthreads();
        if (kt < qt) { load_kv(st ^ 1, kt + 1); CP_COMMIT(); }

        // ---- S = Q K^T : 8 n-tiles x 8 k-steps ----
        float c[8][4];
        #pragma unroll
        for (int ni = 0; ni < 8; ++ni)
            #pragma unroll
            for (int r = 0; r < 4; ++r) c[ni][r] = 0.f;

        const uint32_t kb_base = ks_u +
            (uint32_t)((st * 64 * AT_LQ + b_row * AT_LQ + b_c8) * 2);
        #pragma unroll
        for (int ks = 0; ks < 8; ++ks) {
            uint32_t af[4], bf[8][2];
            LDSM4(af[0], af[1], af[2], af[3], qa_base + (uint32_t)(ks * 32));
            #pragma unroll
            for (int nj = 0; nj < 4; ++nj)
                LDSM4(bf[2 * nj][0], bf[2 * nj][1], bf[2 * nj + 1][0], bf[2 * nj + 1][1],
                      kb_base + (uint32_t)(nj * 16 * AT_LQ * 2 + ks * 32));
            #pragma unroll
            for (int ni = 0; ni < 8; ++ni)
                mma_f16_16n8k16(c[ni], af, bf[ni]);
        }

        if (kt == qt) {   // causal mask on diagonal tile
            #pragma unroll
            for (int r = 0; r < 2; ++r) {
                const int rloc = 16 * warp + g + 8 * r;
                #pragma unroll
                for (int ni = 0; ni < 8; ++ni) {
                    const int cloc = ni * 8 + 2 * t4;
                    if (cloc     > rloc) c[ni][2 * r]     = -INFINITY;
                    if (cloc + 1 > rloc) c[ni][2 * r + 1] = -INFINITY;
                }
            }
        }

        // ---- online softmax (fp32, in-register + quad shuffle) ----
        #pragma unroll
        for (int r = 0; r < 2; ++r) {
            float mt = -INFINITY;
            #pragma unroll
            for (int ni = 0; ni < 8; ++ni)
                mt = fmaxf(mt, fmaxf(c[ni][2 * r], c[ni][2 * r + 1]));
            mt = fmaxf(mt, __shfl_xor_sync(0xffffffffu, mt, 1));
            mt = fmaxf(mt, __shfl_xor_sync(0xffffffffu, mt, 2));
            const float mn = fmaxf(m_i[r], mt);
            const float corr = __expf(m_i[r] - mn);
            float rs = 0.f;
            #pragma unroll
            for (int ni = 0; ni < 8; ++ni) {
                float p0 = __expf(c[ni][2 * r]     - mn);
                float p1 = __expf(c[ni][2 * r + 1] - mn);
                rs += p0 + p1;
                *(__half2*)&Ps[(16 * warp + g + 8 * r) * AT_LV + ni * 8 + 2 * t4] =
                    __floats2half2_rn(p0, p1);
            }
            rs += __shfl_xor_sync(0xffffffffu, rs, 1);
            rs += __shfl_xor_sync(0xffffffffu, rs, 2);
            l_i[r] = l_i[r] * corr + rs;
            m_i[r] = mn;
            #pragma unroll
            for (int ni = 0; ni < 16; ++ni) {
                o[ni][2 * r]     *= corr;
                o[ni][2 * r + 1] *= corr;
            }
        }
        __syncwarp();   // P rows are warp-private: order stores before ldmatrix

        // ---- O += P V : 16 n-tiles x 4 k-steps ----
        const uint32_t vb_base = vs_u +
            (uint32_t)((st * 128 * AT_LV + b_row * AT_LV + b_c8) * 2);
        #pragma unroll
        for (int ks = 0; ks < 4; ++ks) {
            uint32_t af[4], bf[16][2];
            LDSM4(af[0], af[1], af[2], af[3], pa_base + (uint32_t)(ks * 32));
            #pragma unroll
            for (int nj = 0; nj < 8; ++nj)
                LDSM4(bf[2 * nj][0], bf[2 * nj][1], bf[2 * nj + 1][0], bf[2 * nj + 1][1],
                      vb_base + (uint32_t)(nj * 16 * AT_LV * 2 + ks * 32));
            #pragma unroll
            for (int ni = 0; ni < 16; ++ni)
                mma_f16_16n8k16(o[ni], af, bf[ni]);
        }
    }

    // ---- normalize + store ctx (fp16) ----
    #pragma unroll
    for (int r = 0; r < 2; ++r) {
        const float inv = 1.f / l_i[r];
        const int row = qt * 64 + 16 * warp + g + 8 * r;
        __half* obase = g_ctxh + (size_t)(b * Ss + row) * Hh + h * HDd;
        #pragma unroll
        for (int ni = 0; ni < 16; ++ni) {
            const int col = ni * 8 + 2 * t4;
            *(__half2*)&obase[col] = __floats2half2_rn(o[ni][2 * r] * inv,
                                                       o[ni][2 * r + 1] * inv);
        }
    }
}

// ---------------------------------------------------------------------------
extern "C" void kernel_launch(void* const* d_in, const int* in_sizes, int n_in,
                              void* d_out, int out_size) {
    const float* hs  = (const float*)d_in[0];
    const float* res = (const float*)d_in[1];
    const float* Wq  = (const float*)d_in[3];
    const float* Wkv = (const float*)d_in[4];
    const float* Wd  = (const float*)d_in[5];
    const float* bd  = (const float*)d_in[6];
    float* out = (float*)d_out;

    float* qkvp;
    __half *hsh, *wt, *wdt, *ctxh;
    cudaGetSymbolAddress((void**)&qkvp, g_qkv);
    cudaGetSymbolAddress((void**)&hsh,  g_hsh);
    cudaGetSymbolAddress((void**)&wt,   g_wt);
    cudaGetSymbolAddress((void**)&wdt,  g_wdt);
    cudaGetSymbolAddress((void**)&ctxh, g_ctxh);

    cudaFuncSetAttribute(attn_f16_kernel, cudaFuncAttributeMaxDynamicSharedMemorySize, AT_SMEM_BYTES);
    cudaFuncSetAttribute(gemm_f16_kernel, cudaFuncAttributeMaxDynamicSharedMemorySize, GSMEM_BYTES);

    const int NKV = 2 * KVHh * HDd;   // 2048

    rope_table_kernel<<<(Ss * 64 + 255) / 256, 256>>>();
    cvt_h_kernel<<<(Mtot * Hh / 4 + 255) / 256, 256>>>(hs, hsh, Mtot * Hh / 4);
    transpose_h_kernel<<<dim3(Hh / 32, Hh / 32), dim3(32, 8)>>>(Wq,  wt,            Hh, Hh);
    transpose_h_kernel<<<dim3(NKV / 32, Hh / 32), dim3(32, 8)>>>(Wkv, wt + (size_t)Hh * Hh, Hh, NKV);
    transpose_h_kernel<<<dim3(Hh / 32, Hh / 32), dim3(32, 8)>>>(Wd,  wdt,           Hh, Hh);

    // fused QKV projection: C[4096][6144]
    gemm_f16_kernel<<<dim3(NQKV / BN, Mtot / BM), 256, GSMEM_BYTES>>>(
        hsh, wt, qkvp, NQKV, Hh, nullptr, nullptr);

    rope_apply_kernel<<<(Bb * Ss * (NHh + KVHh) * 64 + 255) / 256, 256>>>();
    vtrans_kernel<<<dim3(Ss / 32, HDd / 32, Bb * KVHh), dim3(32, 8)>>>();

    attn_f16_kernel<<<dim3(Ss / 64, NHh, Bb), 128, AT_SMEM_BYTES>>>();

    gemm_f16_kernel<<<dim3(Hh / BN, Mtot / BM), 256, GSMEM_BYTES>>>(
        ctxh, wdt, out, Hh, Hh, bd, res);
}